// round 9
// baseline (speedup 1.0000x reference)
#include <cuda_runtime.h>
#include <cuda_bf16.h>
#include <cstdint>

#define BB 4096
#define DD 4096
#define HH 4096
#define OO 1000
#define PP 2048

typedef __nv_bfloat16 bf;

// ---- device scratch ----
__device__ bf g_Wr1h[(size_t)HH*DD], g_Wr1l[(size_t)HH*DD];
__device__ bf g_Wlvh[(size_t)PP*HH], g_Wlvl[(size_t)PP*HH];
__device__ bf g_Wg1h[(size_t)HH*DD], g_Wg1l[(size_t)HH*DD];
__device__ bf g_Wch [(size_t)2*DD*HH], g_Wcl [(size_t)2*DD*HH]; // Wm/Wl row-interleaved
__device__ bf g_W1h [(size_t)HH*DD], g_W1l [(size_t)HH*DD];
__device__ bf g_W2h [(size_t)OO*HH], g_W2l [(size_t)OO*HH];
__device__ bf g_pTh [(size_t)DD*PP], g_pTl [(size_t)DD*PP];
__device__ bf g_xah[(size_t)BB*DD], g_xal[(size_t)BB*DD];
__device__ bf g_hh [(size_t)BB*HH], g_hl [(size_t)BB*HH];
__device__ bf g_wvh[(size_t)BB*PP], g_wvl[(size_t)BB*PP];
__device__ bf g_xrh[(size_t)BB*DD], g_xrl[(size_t)BB*DD];
__device__ bf g_hrh[(size_t)BB*HH], g_hrl[(size_t)BB*HH];
__device__ bf g_cbh[(size_t)BB*DD], g_cbl[(size_t)BB*DD];
__device__ float g_xrecf[(size_t)BB*DD];
__device__ float g_bcat[2*DD];
__device__ int g_na, g_perm[BB], g_newpos[BB], g_act[BB], g_posinact[BB], g_mask[BB];

// ---- helpers ----
__device__ __forceinline__ float softplusf(float z) {
    return fmaxf(z, 0.0f) + log1pf(expf(-fabsf(z)));
}
__device__ __forceinline__ uint32_t smem_u32(const void* p) {
    uint32_t a;
    asm("{ .reg .u64 t; cvta.to.shared.u64 t, %1; cvt.u32.u64 %0, t; }" : "=r"(a) : "l"(p));
    return a;
}
__device__ __forceinline__ void cpa16(uint32_t dst, const void* src) {
    asm volatile("cp.async.cg.shared.global [%0], [%1], 16;" :: "r"(dst), "l"(src));
}
__device__ __forceinline__ void ldmx4(uint32_t* r, uint32_t a) {
    asm volatile("ldmatrix.sync.aligned.m8n8.x4.shared.b16 {%0,%1,%2,%3}, [%4];"
                 : "=r"(r[0]), "=r"(r[1]), "=r"(r[2]), "=r"(r[3]) : "r"(a));
}
__device__ __forceinline__ void mma16816(float* c, const uint32_t* a, const uint32_t* b) {
    asm("mma.sync.aligned.m16n8k16.row.col.f32.bf16.bf16.f32 "
        "{%0,%1,%2,%3}, {%4,%5,%6,%7}, {%8,%9}, {%0,%1,%2,%3};"
        : "+f"(c[0]), "+f"(c[1]), "+f"(c[2]), "+f"(c[3])
        : "r"(a[0]), "r"(a[1]), "r"(a[2]), "r"(a[3]), "r"(b[0]), "r"(b[1]));
}
__device__ __forceinline__ void split_bf16(float v, bf& h, bf& l) {
    h = __float2bfloat16_rn(v);
    l = __float2bfloat16_rn(v - __bfloat162float(h));
}

// ---- setup ----
__global__ void setup_kernel(const int* __restrict__ mm) {
    __shared__ int wsum[32];
    __shared__ int sTot[2];
    int tid = threadIdx.x, lane = tid & 31, warp = tid >> 5;
    int base = tid * 4;
    int f[4], incl[4], s = 0;
#pragma unroll
    for (int j = 0; j < 4; ++j) { f[j] = (mm[base + j] % 2 != 0); s += f[j]; incl[j] = s; }
    int v = s;
#pragma unroll
    for (int o = 1; o < 32; o <<= 1) { int u = __shfl_up_sync(~0u, v, o); if (lane >= o) v += u; }
    if (lane == 31) wsum[warp] = v;
    __syncthreads();
    if (warp == 0) {
        int w = wsum[lane];
#pragma unroll
        for (int o = 1; o < 32; o <<= 1) { int u = __shfl_up_sync(~0u, w, o); if (lane >= o) w += u; }
        wsum[lane] = w;
        if (lane == 31) sTot[0] = w;
    }
    __syncthreads();
    int Z = BB - sTot[0];
    int thrExcl = (warp ? wsum[warp - 1] : 0) + (v - s);
    int af[4];
#pragma unroll
    for (int j = 0; j < 4; ++j) {
        int i = base + j;
        int ones = thrExcl + incl[j] - f[j];
        int pos = f[j] ? (Z + ones) : (i - ones);
        g_mask[i] = f[j]; g_newpos[i] = pos; g_perm[pos] = i;
        af[j] = (f[j] || pos >= BB / 2);
    }
    __syncthreads();
    int incl2[4], s2 = 0;
#pragma unroll
    for (int j = 0; j < 4; ++j) { s2 += af[j]; incl2[j] = s2; }
    int v2 = s2;
#pragma unroll
    for (int o = 1; o < 32; o <<= 1) { int u = __shfl_up_sync(~0u, v2, o); if (lane >= o) v2 += u; }
    if (lane == 31) wsum[warp] = v2;
    __syncthreads();
    if (warp == 0) {
        int w = wsum[lane];
#pragma unroll
        for (int o = 1; o < 32; o <<= 1) { int u = __shfl_up_sync(~0u, w, o); if (lane >= o) w += u; }
        wsum[lane] = w;
        if (lane == 31) sTot[1] = w;
    }
    __syncthreads();
    int thrExcl2 = (warp ? wsum[warp - 1] : 0) + (v2 - s2);
#pragma unroll
    for (int j = 0; j < 4; ++j) {
        int i = base + j;
        int ab = thrExcl2 + incl2[j] - af[j];
        if (af[j]) { g_act[ab] = i; g_posinact[i] = ab; } else g_posinact[i] = -1;
    }
    if (tid == 0) g_na = sTot[1];
}

// ---- batched weight conversion (one launch) ----
__global__ void convw_all(const float* __restrict__ Wr1, const float* __restrict__ Wlv,
                          const float* __restrict__ Wg1, const float* __restrict__ Wm,
                          const float* __restrict__ Wl,  const float* __restrict__ W1,
                          const float* __restrict__ W2) {
    int seg = blockIdx.y;
    size_t i = ((size_t)blockIdx.x * 256 + threadIdx.x) * 4;
    const float* src;
    bf *hi, *lo;
    size_t n;
    bool ileave = false;
    switch (seg) {
        case 0: src = Wr1; hi = g_Wr1h; lo = g_Wr1l; n = (size_t)HH * DD; break;
        case 1: src = Wg1; hi = g_Wg1h; lo = g_Wg1l; n = (size_t)HH * DD; break;
        case 2: src = W1;  hi = g_W1h;  lo = g_W1l;  n = (size_t)HH * DD; break;
        case 3: src = Wlv; hi = g_Wlvh; lo = g_Wlvl; n = (size_t)PP * HH; break;
        case 4: src = W2;  hi = g_W2h;  lo = g_W2l;  n = (size_t)OO * HH; break;
        case 5: src = Wm;  hi = g_Wch;  lo = g_Wcl;  n = (size_t)DD * HH; ileave = true; break;
        default: src = Wl; hi = g_Wch;  lo = g_Wcl;  n = (size_t)DD * HH; ileave = true; break;
    }
    if (i >= n) return;
    float4 v = *reinterpret_cast<const float4*>(src + i);
    float vv[4] = {v.x, v.y, v.z, v.w};
    bf h[4], l[4];
#pragma unroll
    for (int j = 0; j < 4; ++j) split_bf16(vv[j], h[j], l[j]);
    size_t o = i;
    if (ileave) {
        size_t row = i / HH, col = i - row * HH;
        o = (row * 2 + (seg - 5)) * HH + col;
    }
    reinterpret_cast<__nv_bfloat162*>(hi + o)[0] = __nv_bfloat162(h[0], h[1]);
    reinterpret_cast<__nv_bfloat162*>(hi + o)[1] = __nv_bfloat162(h[2], h[3]);
    reinterpret_cast<__nv_bfloat162*>(lo + o)[0] = __nv_bfloat162(l[0], l[1]);
    reinterpret_cast<__nv_bfloat162*>(lo + o)[1] = __nv_bfloat162(l[2], l[3]);
}

__global__ void convx_kernel(const float* __restrict__ x) {
    int i = blockIdx.y;
    if (i >= g_na) return;
    int r = g_act[i];
    int d = (blockIdx.x * 256 + threadIdx.x) * 4;
    float4 v = *reinterpret_cast<const float4*>(x + (size_t)r * DD + d);
    float vv[4] = {v.x, v.y, v.z, v.w};
    bf h[4], l[4];
#pragma unroll
    for (int j = 0; j < 4; ++j) split_bf16(vv[j], h[j], l[j]);
    size_t o = (size_t)i * DD + d;
    reinterpret_cast<__nv_bfloat162*>(g_xah + o)[0] = __nv_bfloat162(h[0], h[1]);
    reinterpret_cast<__nv_bfloat162*>(g_xah + o)[1] = __nv_bfloat162(h[2], h[3]);
    reinterpret_cast<__nv_bfloat162*>(g_xal + o)[0] = __nv_bfloat162(l[0], l[1]);
    reinterpret_cast<__nv_bfloat162*>(g_xal + o)[1] = __nv_bfloat162(l[2], l[3]);
}
__global__ void convpT_kernel(const float* __restrict__ P) {
    __shared__ float tile[32][33];
    int d0 = blockIdx.x * 32, p0 = blockIdx.y * 32;
    int tx = threadIdx.x, ty = threadIdx.y;
#pragma unroll
    for (int i = 0; i < 4; ++i)
        tile[ty + i * 8][tx] = P[(size_t)(p0 + ty + i * 8) * DD + d0 + tx];
    __syncthreads();
#pragma unroll
    for (int i = 0; i < 4; ++i) {
        bf h, l;
        split_bf16(tile[tx][ty + i * 8], h, l);
        size_t o = (size_t)(d0 + ty + i * 8) * PP + p0 + tx;
        g_pTh[o] = h; g_pTl[o] = l;
    }
}
__global__ void concatb_kernel(const float* __restrict__ a, const float* __restrict__ b) {
    int i = blockIdx.x * 256 + threadIdx.x;   // interleaved: even=bm, odd=bl
    g_bcat[i] = (i & 1) ? b[i >> 1] : a[i >> 1];
}

// ---- mma.sync GEMM: C[M,N] = A @ B^T, bf16 hi/lo 3-product ----
// 64x128 CTA tile, 256 threads (8 warps, 32x32 warp tiles), 3-stage, 2 CTAs/SM
// flags: 1=Meff from g_na, 2=relu, 4=f32 out, 8=hi/lo out, 16=var/w, 32=xreg-fused dual
#define ROWB 80
#define ATILE_B (64 * ROWB)      // 5120
#define BTILE_B (128 * ROWB)     // 10240
#define BOFF (2 * ATILE_B)       // 10240
#define STAGE_B (2 * ATILE_B + 2 * BTILE_B)   // 30720
#define NSTG 3
#define SMEMB (NSTG * STAGE_B + 512)

__global__ void __launch_bounds__(256, 2)
gemm_mma(const bf* __restrict__ Ah, const bf* __restrict__ Al,
         const bf* __restrict__ Bh, const bf* __restrict__ Bl,
         const float* __restrict__ bias, float* __restrict__ Cf,
         bf* __restrict__ Ch, bf* __restrict__ Cl,
         float* __restrict__ Cw, const float* __restrict__ eps,
         int M, int N, int K, int flags)
{
    int Meff = (flags & 1) ? g_na : M;
    int mT = blockIdx.y * 64;
    if (mT >= Meff) return;
    int nT = blockIdx.x * 128;

    extern __shared__ char sm[];
    uint32_t sb = smem_u32(sm);
    float* biasS = reinterpret_cast<float*>(sm + NSTG * STAGE_B);

    int tid = threadIdx.x, wid = tid >> 5, lane = tid & 31;
    int wm = wid & 1, wn = wid >> 1;   // warp tile: 32 rows, 32 cols

    if (tid < 128) {
        int n = nT + tid;
        biasS[tid] = (bias && n < N) ? bias[n] : 0.0f;
    }

    uint32_t aBase = (wm * 32 + (lane & 15)) * ROWB + ((lane >> 4) & 1) * 16;
    uint32_t bBase = BOFF + (wn * 32 + ((lane >> 4) & 1) * 8 + (lane & 7)) * ROWB +
                     ((lane >> 3) & 1) * 16;

    float acc[2][4][4];
#pragma unroll
    for (int a = 0; a < 2; ++a)
#pragma unroll
        for (int b = 0; b < 4; ++b)
#pragma unroll
            for (int c = 0; c < 4; ++c) acc[a][b][c] = 0.0f;

    int nK = K / 32;

#define LOAD_STAGE(s, k0)                                                        \
    {                                                                            \
        uint32_t st = sb + (s) * STAGE_B;                                        \
        {                                                                        \
            int r = tid >> 2, c16 = tid & 3;                                     \
            int rg = mT + r; rg = rg < Meff ? rg : Meff - 1;                     \
            size_t go = (size_t)rg * K + (k0) + c16 * 8;                         \
            uint32_t off = r * ROWB + c16 * 16;                                  \
            cpa16(st + off, Ah + go);                                            \
            cpa16(st + ATILE_B + off, Al + go);                                  \
        }                                                                        \
        _Pragma("unroll")                                                        \
        for (int i = 0; i < 2; ++i) {                                            \
            int ch = i * 256 + tid;                                              \
            int r = ch >> 2, c16 = ch & 3;                                       \
            int rg = nT + r; rg = rg < N ? rg : N - 1;                           \
            size_t go = (size_t)rg * K + (k0) + c16 * 8;                         \
            uint32_t off = r * ROWB + c16 * 16;                                  \
            cpa16(st + BOFF + off, Bh + go);                                     \
            cpa16(st + BOFF + BTILE_B + off, Bl + go);                           \
        }                                                                        \
    }

#define LOAD_FRAGS(st, kh, AH, AL, BH, BL)                                       \
    {                                                                            \
        uint32_t ab = (st) + aBase + (kh) * 32;                                  \
        _Pragma("unroll")                                                        \
        for (int ma = 0; ma < 2; ++ma) {                                         \
            ldmx4(AH[ma], ab + ma * 16 * ROWB);                                  \
            ldmx4(AL[ma], ab + ma * 16 * ROWB + ATILE_B);                        \
        }                                                                        \
        uint32_t bb = (st) + bBase + (kh) * 32;                                  \
        _Pragma("unroll")                                                        \
        for (int p = 0; p < 2; ++p) {                                            \
            uint32_t t[4];                                                       \
            ldmx4(t, bb + p * 16 * ROWB);                                        \
            BH[2*p][0] = t[0]; BH[2*p][1] = t[1];                                \
            BH[2*p+1][0] = t[2]; BH[2*p+1][1] = t[3];                            \
            ldmx4(t, bb + p * 16 * ROWB + BTILE_B);                              \
            BL[2*p][0] = t[0]; BL[2*p][1] = t[1];                                \
            BL[2*p+1][0] = t[2]; BL[2*p+1][1] = t[3];                            \
        }                                                                        \
    }

#define MMA_BLOCK(AH, AL, BH, BL)                                                \
    {                                                                            \
        _Pragma("unroll")                                                        \
        for (int ma = 0; ma < 2; ++ma)                                           \
            _Pragma("unroll")                                                    \
            for (int na = 0; na < 4; ++na) mma16816(acc[ma][na], AH[ma], BH[na]);\
        _Pragma("unroll")                                                        \
        for (int ma = 0; ma < 2; ++ma)                                           \
            _Pragma("unroll")                                                    \
            for (int na = 0; na < 4; ++na) mma16816(acc[ma][na], AH[ma], BL[na]);\
        _Pragma("unroll")                                                        \
        for (int ma = 0; ma < 2; ++ma)                                           \
            _Pragma("unroll")                                                    \
            for (int na = 0; na < 4; ++na) mma16816(acc[ma][na], AL[ma], BH[na]);\
    }

    LOAD_STAGE(0, 0);
    asm volatile("cp.async.commit_group;");
    LOAD_STAGE(1, 32);
    asm volatile("cp.async.commit_group;");

    uint32_t a0h[2][4], a0l[2][4], b0h[4][2], b0l[4][2];
    uint32_t a1h[2][4], a1l[2][4], b1h[4][2], b1l[4][2];

    asm volatile("cp.async.wait_group 1;");
    __syncthreads();
    LOAD_FRAGS(sb, 0, a0h, a0l, b0h, b0l);

    int s_cur = 0, s_nxt2 = 2;   // stage idx of it, and of it+2
#pragma unroll 1
    for (int it = 0; it < nK; ++it) {
        uint32_t st = sb + s_cur * STAGE_B;
        LOAD_FRAGS(st, 1, a1h, a1l, b1h, b1l);
        int ps = it + 2;
        if (ps < nK) LOAD_STAGE(s_nxt2, ps * 32);
        asm volatile("cp.async.commit_group;");
        MMA_BLOCK(a0h, a0l, b0h, b0l);
        asm volatile("cp.async.wait_group 1;");
        __syncthreads();
        if (it + 1 < nK) {
            int s_n = s_cur + 1 == NSTG ? 0 : s_cur + 1;
            uint32_t st2 = sb + s_n * STAGE_B;
            LOAD_FRAGS(st2, 0, a0h, a0l, b0h, b0l);
        }
        MMA_BLOCK(a1h, a1l, b1h, b1l);
        s_cur = s_cur + 1 == NSTG ? 0 : s_cur + 1;
        s_nxt2 = s_nxt2 + 1 == NSTG ? 0 : s_nxt2 + 1;
    }

    // ---- epilogue ----
    bool relu = flags & 2, f32s = flags & 4, hilos = flags & 8;
    bool varw = flags & 16, dual = flags & 32;
#pragma unroll
    for (int ma = 0; ma < 2; ++ma) {
#pragma unroll
        for (int rs = 0; rs < 2; ++rs) {
            int m = mT + wm * 32 + ma * 16 + (lane >> 2) + rs * 8;
            if (m >= Meff) continue;
            size_t ro = (size_t)m * N;
            int r = (varw || dual) ? g_act[m] : 0;
#pragma unroll
            for (int na = 0; na < 4; ++na) {
                int nc = wn * 32 + na * 8 + (lane & 3) * 2;
                int n = nT + nc;
                if (n >= N) continue;
                float v0 = acc[ma][na][rs * 2 + 0] + biasS[nc];
                float v1 = acc[ma][na][rs * 2 + 1] + biasS[nc + 1];
                if (relu) { v0 = fmaxf(v0, 0.0f); v1 = fmaxf(v1, 0.0f); }
                if (dual) {
                    if (g_mask[r]) {
                        int d = n >> 1;
                        float xr = Cf[(size_t)m * DD + d];
                        float ep = eps[(size_t)r * DD + d];
                        float o = xr * softplusf(v0 + expf(0.5f * v1) * ep);
                        bf h, l;
                        split_bf16(o, h, l);
                        size_t dst = (size_t)g_newpos[r] * DD + d;
                        Ch[dst] = h;
                        Cl[dst] = l;
                    }
                } else if (varw) {
                    float var0 = expf(v0), var1 = expf(v1);
                    float w0 = 1.0f + sqrtf(var0) * eps[(size_t)r * N + n];
                    float w1 = 1.0f + sqrtf(var1) * eps[(size_t)r * N + n + 1];
                    int np = g_newpos[r];
                    if (np >= BB / 2) {
                        size_t jo = (size_t)(np - BB / 2) * N + n;
                        *reinterpret_cast<float2*>(Cf + jo) = make_float2(var0, var1);
                        *reinterpret_cast<float2*>(Cw + jo) = make_float2(w0, w1);
                    }
                    bf h0, l0, h1, l1;
                    split_bf16(w0, h0, l0); split_bf16(w1, h1, l1);
                    *reinterpret_cast<__nv_bfloat162*>(Ch + ro + n) = __nv_bfloat162(h0, h1);
                    *reinterpret_cast<__nv_bfloat162*>(Cl + ro + n) = __nv_bfloat162(l0, l1);
                } else {
                    if (f32s) {
                        *reinterpret_cast<float2*>(Cf + ro + n) = make_float2(v0, v1);
                    }
                    if (hilos) {
                        bf h0, l0, h1, l1;
                        split_bf16(v0, h0, l0); split_bf16(v1, h1, l1);
                        *reinterpret_cast<__nv_bfloat162*>(Ch + ro + n) = __nv_bfloat162(h0, h1);
                        *reinterpret_cast<__nv_bfloat162*>(Cl + ro + n) = __nv_bfloat162(l0, l1);
                    }
                }
            }
        }
    }
}

// ---- elementwise ----
__global__ void copy_kernel(const float* __restrict__ x) {
    int j = blockIdx.y;
    int r = g_perm[j];
    if (g_mask[r]) return;
    int d = (blockIdx.x * 256 + threadIdx.x) * 4;
    float4 v = *reinterpret_cast<const float4*>(x + (size_t)r * DD + d);
    float vv[4] = {v.x, v.y, v.z, v.w};
    bf h[4], l[4];
#pragma unroll
    for (int i = 0; i < 4; ++i) split_bf16(vv[i], h[i], l[i]);
    size_t dst = (size_t)j * DD + d;
    reinterpret_cast<__nv_bfloat162*>(g_cbh + dst)[0] = __nv_bfloat162(h[0], h[1]);
    reinterpret_cast<__nv_bfloat162*>(g_cbh + dst)[1] = __nv_bfloat162(h[2], h[3]);
    reinterpret_cast<__nv_bfloat162*>(g_cbl + dst)[0] = __nv_bfloat162(l[0], l[1]);
    reinterpret_cast<__nv_bfloat162*>(g_cbl + dst)[1] = __nv_bfloat162(l[2], l[3]);
}

// ---- launch ----
static void* sa(const void* s) { void* p = nullptr; cudaGetSymbolAddress(&p, s); return p; }

extern "C" void kernel_launch(void* const* d_in, const int* in_sizes, int n_in,
                              void* d_out, int out_size) {
    const float* x      = (const float*)d_in[0];
    const int*   mm     = (const int*)d_in[1];
    const float* priors = (const float*)d_in[2];
    const float* W1  = (const float*)d_in[3];
    const float* b1  = (const float*)d_in[4];
    const float* W2  = (const float*)d_in[5];
    const float* b2  = (const float*)d_in[6];
    const float* Wr1 = (const float*)d_in[7];
    const float* br1 = (const float*)d_in[8];
    const float* Wlv = (const float*)d_in[9];
    const float* blv = (const float*)d_in[10];
    const float* Wg1 = (const float*)d_in[11];
    const float* bg1 = (const float*)d_in[12];
    const float* Wm  = (const float*)d_in[13];
    const float* bm  = (const float*)d_in[14];
    const float* Wl  = (const float*)d_in[15];
    const float* bl  = (const float*)d_in[16];
    const float* eps_w = (const float*)d_in[17];
    const float* eps_r = (const float*)d_in[18];
    float* out = (float*)d_out;
    float* out_logits = out;
    float* out_w = out + (size_t)BB * OO;
    float* out_var = out_w + (size_t)(BB - BB / 2) * PP;

    cudaFuncSetAttribute(gemm_mma, cudaFuncAttributeMaxDynamicSharedMemorySize, SMEMB);

    bf *Wr1h=(bf*)sa(g_Wr1h), *Wr1l=(bf*)sa(g_Wr1l), *Wlvh=(bf*)sa(g_Wlvh), *Wlvl=(bf*)sa(g_Wlvl);
    bf *Wg1h=(bf*)sa(g_Wg1h), *Wg1l=(bf*)sa(g_Wg1l);
    bf *Wch=(bf*)sa(g_Wch), *Wcl=(bf*)sa(g_Wcl);
    bf *W1h=(bf*)sa(g_W1h), *W1l=(bf*)sa(g_W1l);
    bf *W2h=(bf*)sa(g_W2h), *W2l=(bf*)sa(g_W2l), *pTh=(bf*)sa(g_pTh), *pTl=(bf*)sa(g_pTl);
    bf *xah=(bf*)sa(g_xah), *xal=(bf*)sa(g_xal), *hh=(bf*)sa(g_hh), *hl=(bf*)sa(g_hl);
    bf *wvh=(bf*)sa(g_wvh), *wvl=(bf*)sa(g_wvl), *xrh=(bf*)sa(g_xrh), *xrl=(bf*)sa(g_xrl);
    bf *hrh=(bf*)sa(g_hrh), *hrl=(bf*)sa(g_hrl), *cbh=(bf*)sa(g_cbh), *cbl=(bf*)sa(g_cbl);
    float *pxrecf=(float*)sa(g_xrecf);
    float *pbcat=(float*)sa(g_bcat);

    dim3 blk(256);
    const int MT = BB / 64;   // 64 m-tiles

    setup_kernel<<<1, 1024>>>(mm);                                  // 0
    convx_kernel<<<dim3(DD/1024, BB), 256>>>(x);                    // 1
    convw_all<<<dim3(16384, 7), 256>>>(Wr1, Wlv, Wg1, Wm, Wl, W1, W2); // 2
    // 3) h = relu(xa @ Wr1^T + br1) -> hi/lo   [launch index 3 = PROFILED]
    gemm_mma<<<dim3(HH/128, MT), blk, SMEMB>>>(xah, xal, Wr1h, Wr1l, br1,
        nullptr, hh, hl, nullptr, nullptr, BB, HH, DD, 1|2|8);
    // 4) var/w: direct out_var/out_w + wv hi/lo
    gemm_mma<<<dim3(PP/128, MT), blk, SMEMB>>>(hh, hl, Wlvh, Wlvl, blv,
        out_var, wvh, wvl, out_w, eps_w, BB, PP, HH, 1|16);
    convpT_kernel<<<dim3(DD/32, PP/32), dim3(32, 8)>>>(priors);     // 5
    // 6) x_rec = w @ pT^T -> f32 + hi/lo
    gemm_mma<<<dim3(DD/128, MT), blk, SMEMB>>>(wvh, wvl, pTh, pTl, nullptr,
        pxrecf, xrh, xrl, nullptr, nullptr, BB, DD, PP, 1|4|8);
    // 7) hr = relu(x_rec @ Wg1^T + bg1)
    gemm_mma<<<dim3(HH/128, MT), blk, SMEMB>>>(xrh, xrl, Wg1h, Wg1l, bg1,
        nullptr, hrh, hrl, nullptr, nullptr, BB, HH, DD, 1|2|8);
    concatb_kernel<<<(2*DD)/256, 256>>>(bm, bl);                    // 8
    // 9) fused dual: interleaved [mean|lreg] -> x_reg scatter into cbh/cbl
    gemm_mma<<<dim3((2*DD)/128, MT), blk, SMEMB>>>(hrh, hrl, Wch, Wcl, pbcat,
        pxrecf, cbh, cbl, nullptr, eps_r, BB, 2*DD, HH, 1|32);
    copy_kernel<<<dim3(DD/1024, BB), 256>>>(x);                     // 10
    // 11) h1 = relu(comb @ W1^T + b1) (reuse hh/hl)
    gemm_mma<<<dim3(HH/128, MT), blk, SMEMB>>>(cbh, cbl, W1h, W1l, b1,
        nullptr, hh, hl, nullptr, nullptr, BB, HH, DD, 2|8);
    // 12) logits
    gemm_mma<<<dim3((OO+127)/128, MT), blk, SMEMB>>>(hh, hl, W2h, W2l, b2,
        out_logits, nullptr, nullptr, nullptr, nullptr, BB, OO, HH, 4);
}

// round 10
// speedup vs baseline: 1.1510x; 1.1510x over previous
#include <cuda_runtime.h>
#include <cuda_bf16.h>
#include <cstdint>

#define BB 4096
#define DD 4096
#define HH 4096
#define OO 1000
#define PP 2048

typedef __nv_bfloat16 bf;

// ---- device scratch ----
__device__ bf g_Wr1h[(size_t)HH*DD], g_Wr1l[(size_t)HH*DD];
__device__ bf g_Wlvh[(size_t)PP*HH], g_Wlvl[(size_t)PP*HH];
__device__ bf g_Wg1h[(size_t)HH*DD], g_Wg1l[(size_t)HH*DD];
__device__ bf g_Wch [(size_t)2*DD*HH], g_Wcl [(size_t)2*DD*HH]; // Wm/Wl row-interleaved
__device__ bf g_W1h [(size_t)HH*DD], g_W1l [(size_t)HH*DD];
__device__ bf g_W2h [(size_t)OO*HH], g_W2l [(size_t)OO*HH];
__device__ bf g_pTh [(size_t)DD*PP], g_pTl [(size_t)DD*PP];
__device__ bf g_xah[(size_t)BB*DD], g_xal[(size_t)BB*DD];
__device__ bf g_hh [(size_t)BB*HH], g_hl [(size_t)BB*HH];
__device__ bf g_wvh[(size_t)BB*PP], g_wvl[(size_t)BB*PP];
__device__ bf g_xrh[(size_t)BB*DD], g_xrl[(size_t)BB*DD];
__device__ bf g_hrh[(size_t)BB*HH], g_hrl[(size_t)BB*HH];
__device__ bf g_cbh[(size_t)BB*DD], g_cbl[(size_t)BB*DD];
__device__ float g_xrecf[(size_t)BB*DD];
__device__ float g_bcat[2*DD];
__device__ int g_na, g_perm[BB], g_newpos[BB], g_act[BB], g_posinact[BB], g_mask[BB];

// ---- helpers ----
__device__ __forceinline__ float softplusf(float z) {
    return fmaxf(z, 0.0f) + log1pf(expf(-fabsf(z)));
}
__device__ __forceinline__ uint32_t smem_u32(const void* p) {
    uint32_t a;
    asm("{ .reg .u64 t; cvta.to.shared.u64 t, %1; cvt.u32.u64 %0, t; }" : "=r"(a) : "l"(p));
    return a;
}
__device__ __forceinline__ void cpa16(uint32_t dst, const void* src) {
    asm volatile("cp.async.cg.shared.global [%0], [%1], 16;" :: "r"(dst), "l"(src));
}
__device__ __forceinline__ void ldmx4(uint32_t* r, uint32_t a) {
    asm volatile("ldmatrix.sync.aligned.m8n8.x4.shared.b16 {%0,%1,%2,%3}, [%4];"
                 : "=r"(r[0]), "=r"(r[1]), "=r"(r[2]), "=r"(r[3]) : "r"(a));
}
__device__ __forceinline__ void mma16816(float* c, const uint32_t* a, const uint32_t* b) {
    asm("mma.sync.aligned.m16n8k16.row.col.f32.bf16.bf16.f32 "
        "{%0,%1,%2,%3}, {%4,%5,%6,%7}, {%8,%9}, {%0,%1,%2,%3};"
        : "+f"(c[0]), "+f"(c[1]), "+f"(c[2]), "+f"(c[3])
        : "r"(a[0]), "r"(a[1]), "r"(a[2]), "r"(a[3]), "r"(b[0]), "r"(b[1]));
}
__device__ __forceinline__ void split_bf16(float v, bf& h, bf& l) {
    h = __float2bfloat16_rn(v);
    l = __float2bfloat16_rn(v - __bfloat162float(h));
}

// ---- setup ----
__global__ void setup_kernel(const int* __restrict__ mm) {
    __shared__ int wsum[32];
    __shared__ int sTot[2];
    int tid = threadIdx.x, lane = tid & 31, warp = tid >> 5;
    int base = tid * 4;
    int f[4], incl[4], s = 0;
#pragma unroll
    for (int j = 0; j < 4; ++j) { f[j] = (mm[base + j] % 2 != 0); s += f[j]; incl[j] = s; }
    int v = s;
#pragma unroll
    for (int o = 1; o < 32; o <<= 1) { int u = __shfl_up_sync(~0u, v, o); if (lane >= o) v += u; }
    if (lane == 31) wsum[warp] = v;
    __syncthreads();
    if (warp == 0) {
        int w = wsum[lane];
#pragma unroll
        for (int o = 1; o < 32; o <<= 1) { int u = __shfl_up_sync(~0u, w, o); if (lane >= o) w += u; }
        wsum[lane] = w;
        if (lane == 31) sTot[0] = w;
    }
    __syncthreads();
    int Z = BB - sTot[0];
    int thrExcl = (warp ? wsum[warp - 1] : 0) + (v - s);
    int af[4];
#pragma unroll
    for (int j = 0; j < 4; ++j) {
        int i = base + j;
        int ones = thrExcl + incl[j] - f[j];
        int pos = f[j] ? (Z + ones) : (i - ones);
        g_mask[i] = f[j]; g_newpos[i] = pos; g_perm[pos] = i;
        af[j] = (f[j] || pos >= BB / 2);
    }
    __syncthreads();
    int incl2[4], s2 = 0;
#pragma unroll
    for (int j = 0; j < 4; ++j) { s2 += af[j]; incl2[j] = s2; }
    int v2 = s2;
#pragma unroll
    for (int o = 1; o < 32; o <<= 1) { int u = __shfl_up_sync(~0u, v2, o); if (lane >= o) v2 += u; }
    if (lane == 31) wsum[warp] = v2;
    __syncthreads();
    if (warp == 0) {
        int w = wsum[lane];
#pragma unroll
        for (int o = 1; o < 32; o <<= 1) { int u = __shfl_up_sync(~0u, w, o); if (lane >= o) w += u; }
        wsum[lane] = w;
        if (lane == 31) sTot[1] = w;
    }
    __syncthreads();
    int thrExcl2 = (warp ? wsum[warp - 1] : 0) + (v2 - s2);
#pragma unroll
    for (int j = 0; j < 4; ++j) {
        int i = base + j;
        int ab = thrExcl2 + incl2[j] - af[j];
        if (af[j]) { g_act[ab] = i; g_posinact[i] = ab; } else g_posinact[i] = -1;
    }
    if (tid == 0) g_na = sTot[1];
}

// ---- batched weight conversion (one launch) ----
__global__ void convw_all(const float* __restrict__ Wr1, const float* __restrict__ Wlv,
                          const float* __restrict__ Wg1, const float* __restrict__ Wm,
                          const float* __restrict__ Wl,  const float* __restrict__ W1,
                          const float* __restrict__ W2) {
    int seg = blockIdx.y;
    size_t i = ((size_t)blockIdx.x * 256 + threadIdx.x) * 4;
    const float* src;
    bf *hi, *lo;
    size_t n;
    bool ileave = false;
    switch (seg) {
        case 0: src = Wr1; hi = g_Wr1h; lo = g_Wr1l; n = (size_t)HH * DD; break;
        case 1: src = Wg1; hi = g_Wg1h; lo = g_Wg1l; n = (size_t)HH * DD; break;
        case 2: src = W1;  hi = g_W1h;  lo = g_W1l;  n = (size_t)HH * DD; break;
        case 3: src = Wlv; hi = g_Wlvh; lo = g_Wlvl; n = (size_t)PP * HH; break;
        case 4: src = W2;  hi = g_W2h;  lo = g_W2l;  n = (size_t)OO * HH; break;
        case 5: src = Wm;  hi = g_Wch;  lo = g_Wcl;  n = (size_t)DD * HH; ileave = true; break;
        default: src = Wl; hi = g_Wch;  lo = g_Wcl;  n = (size_t)DD * HH; ileave = true; break;
    }
    if (i >= n) return;
    float4 v = *reinterpret_cast<const float4*>(src + i);
    float vv[4] = {v.x, v.y, v.z, v.w};
    bf h[4], l[4];
#pragma unroll
    for (int j = 0; j < 4; ++j) split_bf16(vv[j], h[j], l[j]);
    size_t o = i;
    if (ileave) {
        size_t row = i / HH, col = i - row * HH;
        o = (row * 2 + (seg - 5)) * HH + col;
    }
    reinterpret_cast<__nv_bfloat162*>(hi + o)[0] = __nv_bfloat162(h[0], h[1]);
    reinterpret_cast<__nv_bfloat162*>(hi + o)[1] = __nv_bfloat162(h[2], h[3]);
    reinterpret_cast<__nv_bfloat162*>(lo + o)[0] = __nv_bfloat162(l[0], l[1]);
    reinterpret_cast<__nv_bfloat162*>(lo + o)[1] = __nv_bfloat162(l[2], l[3]);
}

__global__ void convx_kernel(const float* __restrict__ x) {
    int i = blockIdx.y;
    if (i >= g_na) return;
    int r = g_act[i];
    int d = (blockIdx.x * 256 + threadIdx.x) * 4;
    float4 v = *reinterpret_cast<const float4*>(x + (size_t)r * DD + d);
    float vv[4] = {v.x, v.y, v.z, v.w};
    bf h[4], l[4];
#pragma unroll
    for (int j = 0; j < 4; ++j) split_bf16(vv[j], h[j], l[j]);
    size_t o = (size_t)i * DD + d;
    reinterpret_cast<__nv_bfloat162*>(g_xah + o)[0] = __nv_bfloat162(h[0], h[1]);
    reinterpret_cast<__nv_bfloat162*>(g_xah + o)[1] = __nv_bfloat162(h[2], h[3]);
    reinterpret_cast<__nv_bfloat162*>(g_xal + o)[0] = __nv_bfloat162(l[0], l[1]);
    reinterpret_cast<__nv_bfloat162*>(g_xal + o)[1] = __nv_bfloat162(l[2], l[3]);
}
__global__ void convpT_kernel(const float* __restrict__ P) {
    __shared__ float tile[32][33];
    int d0 = blockIdx.x * 32, p0 = blockIdx.y * 32;
    int tx = threadIdx.x, ty = threadIdx.y;
#pragma unroll
    for (int i = 0; i < 4; ++i)
        tile[ty + i * 8][tx] = P[(size_t)(p0 + ty + i * 8) * DD + d0 + tx];
    __syncthreads();
#pragma unroll
    for (int i = 0; i < 4; ++i) {
        bf h, l;
        split_bf16(tile[tx][ty + i * 8], h, l);
        size_t o = (size_t)(d0 + ty + i * 8) * PP + p0 + tx;
        g_pTh[o] = h; g_pTl[o] = l;
    }
}
__global__ void concatb_kernel(const float* __restrict__ a, const float* __restrict__ b) {
    int i = blockIdx.x * 256 + threadIdx.x;   // interleaved: even=bm, odd=bl
    g_bcat[i] = (i & 1) ? b[i >> 1] : a[i >> 1];
}

// ---- mma.sync GEMM: C[M,N] = A @ B^T, bf16 hi/lo 3-product, 512 threads ----
// 128x128 CTA tile, BK=64 (4 kh-steps/stage), 3-stage pipeline, 1 CTA/SM
// flags: 1=Meff from g_na, 2=relu, 4=f32 out, 8=hi/lo out, 16=var/w, 32=xreg-fused dual
#define ROWB 144                 // 128B data + 16B pad: conflict-free ldmatrix
#define TILE_B (128 * ROWB)      // 18432
#define STAGE_B (4 * TILE_B)     // 73728: Ah, Al, Bh, Bl
#define NSTG 3
#define SMEMB (NSTG * STAGE_B + 512)

__global__ void __launch_bounds__(512, 1)
gemm_mma(const bf* __restrict__ Ah, const bf* __restrict__ Al,
         const bf* __restrict__ Bh, const bf* __restrict__ Bl,
         const float* __restrict__ bias, float* __restrict__ Cf,
         bf* __restrict__ Ch, bf* __restrict__ Cl,
         float* __restrict__ Cw, const float* __restrict__ eps,
         int M, int N, int K, int flags)
{
    int Meff = (flags & 1) ? g_na : M;
    int mT = blockIdx.y * 128;
    if (mT >= Meff) return;
    int nT = blockIdx.x * 128;

    extern __shared__ char sm[];
    uint32_t sb = smem_u32(sm);
    float* biasS = reinterpret_cast<float*>(sm + NSTG * STAGE_B);

    int tid = threadIdx.x, wid = tid >> 5, lane = tid & 31;
    int wm = wid & 3, wn = wid >> 2;

    if (tid < 128) {
        int n = nT + tid;
        biasS[tid] = (bias && n < N) ? bias[n] : 0.0f;
    }

    uint32_t aBase = (wm * 32 + (lane & 15)) * ROWB + ((lane >> 4) & 1) * 16;
    uint32_t bBase = 2 * TILE_B + (wn * 32 + ((lane >> 4) & 1) * 8 + (lane & 7)) * ROWB +
                     ((lane >> 3) & 1) * 16;

    float acc[2][4][4];
#pragma unroll
    for (int a = 0; a < 2; ++a)
#pragma unroll
        for (int b = 0; b < 4; ++b)
#pragma unroll
            for (int c = 0; c < 4; ++c) acc[a][b][c] = 0.0f;

    int nK = K / 64;

#define LOAD_STAGE(s, k0)                                                        \
    {                                                                            \
        uint32_t st = sb + (s) * STAGE_B;                                        \
        _Pragma("unroll")                                                        \
        for (int i = 0; i < 2; ++i) {                                            \
            int idx = i * 512 + tid;                                             \
            int r = idx >> 3, c16 = idx & 7;                                     \
            int rg = mT + r; rg = rg < Meff ? rg : Meff - 1;                     \
            size_t go = (size_t)rg * K + (k0) + c16 * 8;                         \
            uint32_t off = r * ROWB + c16 * 16;                                  \
            cpa16(st + off, Ah + go);                                            \
            cpa16(st + TILE_B + off, Al + go);                                   \
        }                                                                        \
        _Pragma("unroll")                                                        \
        for (int i = 0; i < 2; ++i) {                                            \
            int idx = i * 512 + tid;                                             \
            int r = idx >> 3, c16 = idx & 7;                                     \
            int rg = nT + r; rg = rg < N ? rg : N - 1;                           \
            size_t go = (size_t)rg * K + (k0) + c16 * 8;                         \
            uint32_t off = r * ROWB + c16 * 16;                                  \
            cpa16(st + 2 * TILE_B + off, Bh + go);                               \
            cpa16(st + 3 * TILE_B + off, Bl + go);                               \
        }                                                                        \
    }

#define LOAD_FRAGS(st, kh, AH, AL, BH, BL)                                       \
    {                                                                            \
        uint32_t ab = (st) + aBase + (kh) * 32;                                  \
        _Pragma("unroll")                                                        \
        for (int ma = 0; ma < 2; ++ma) {                                         \
            ldmx4(AH[ma], ab + ma * 16 * ROWB);                                  \
            ldmx4(AL[ma], ab + ma * 16 * ROWB + TILE_B);                         \
        }                                                                        \
        uint32_t bb = (st) + bBase + (kh) * 32;                                  \
        _Pragma("unroll")                                                        \
        for (int p = 0; p < 2; ++p) {                                            \
            uint32_t t[4];                                                       \
            ldmx4(t, bb + p * 16 * ROWB);                                        \
            BH[2*p][0] = t[0]; BH[2*p][1] = t[1];                                \
            BH[2*p+1][0] = t[2]; BH[2*p+1][1] = t[3];                            \
            ldmx4(t, bb + p * 16 * ROWB + TILE_B);                               \
            BL[2*p][0] = t[0]; BL[2*p][1] = t[1];                                \
            BL[2*p+1][0] = t[2]; BL[2*p+1][1] = t[3];                            \
        }                                                                        \
    }

#define MMA_BLOCK(AH, AL, BH, BL)                                                \
    {                                                                            \
        _Pragma("unroll")                                                        \
        for (int ma = 0; ma < 2; ++ma)                                           \
            _Pragma("unroll")                                                    \
            for (int na = 0; na < 4; ++na) mma16816(acc[ma][na], AH[ma], BH[na]);\
        _Pragma("unroll")                                                        \
        for (int ma = 0; ma < 2; ++ma)                                           \
            _Pragma("unroll")                                                    \
            for (int na = 0; na < 4; ++na) mma16816(acc[ma][na], AH[ma], BL[na]);\
        _Pragma("unroll")                                                        \
        for (int ma = 0; ma < 2; ++ma)                                           \
            _Pragma("unroll")                                                    \
            for (int na = 0; na < 4; ++na) mma16816(acc[ma][na], AL[ma], BH[na]);\
    }

    LOAD_STAGE(0, 0);
    asm volatile("cp.async.commit_group;");
    LOAD_STAGE(1, 64);
    asm volatile("cp.async.commit_group;");

    uint32_t a0h[2][4], a0l[2][4], b0h[4][2], b0l[4][2];
    uint32_t a1h[2][4], a1l[2][4], b1h[4][2], b1l[4][2];

    asm volatile("cp.async.wait_group 1;");
    __syncthreads();
    LOAD_FRAGS(sb, 0, a0h, a0l, b0h, b0l);

    int s_cur = 0;
#pragma unroll 1
    for (int it = 0; it < nK; ++it) {
        uint32_t st = sb + s_cur * STAGE_B;
        // kh1..kh3 ping-pong between frag sets
        LOAD_FRAGS(st, 1, a1h, a1l, b1h, b1l);
        MMA_BLOCK(a0h, a0l, b0h, b0l);
        LOAD_FRAGS(st, 2, a0h, a0l, b0h, b0l);
        MMA_BLOCK(a1h, a1l, b1h, b1l);
        LOAD_FRAGS(st, 3, a1h, a1l, b1h, b1l);
        MMA_BLOCK(a0h, a0l, b0h, b0l);
        // prefetch stage it+2 into slot (it+2)%3 (last read in iter it-1, behind barrier)
        int ps = it + 2;
        int s_tgt = s_cur + 2 >= NSTG ? s_cur + 2 - NSTG : s_cur + 2;
        if (ps < nK) LOAD_STAGE(s_tgt, ps * 64);
        asm volatile("cp.async.commit_group;");
        asm volatile("cp.async.wait_group 1;");
        __syncthreads();
        if (it + 1 < nK) {
            int s_n = s_cur + 1 == NSTG ? 0 : s_cur + 1;
            uint32_t st2 = sb + s_n * STAGE_B;
            LOAD_FRAGS(st2, 0, a0h, a0l, b0h, b0l);
        }
        MMA_BLOCK(a1h, a1l, b1h, b1l);
        s_cur = s_cur + 1 == NSTG ? 0 : s_cur + 1;
    }

    // ---- epilogue ----
    bool relu = flags & 2, f32s = flags & 4, hilos = flags & 8;
    bool varw = flags & 16, dual = flags & 32;
#pragma unroll
    for (int ma = 0; ma < 2; ++ma) {
#pragma unroll
        for (int rs = 0; rs < 2; ++rs) {
            int m = mT + wm * 32 + ma * 16 + (lane >> 2) + rs * 8;
            if (m >= Meff) continue;
            size_t ro = (size_t)m * N;
            int r = (varw || dual) ? g_act[m] : 0;
#pragma unroll
            for (int na = 0; na < 4; ++na) {
                int nc = wn * 32 + na * 8 + (lane & 3) * 2;
                int n = nT + nc;
                if (n >= N) continue;
                float v0 = acc[ma][na][rs * 2 + 0] + biasS[nc];
                float v1 = acc[ma][na][rs * 2 + 1] + biasS[nc + 1];
                if (relu) { v0 = fmaxf(v0, 0.0f); v1 = fmaxf(v1, 0.0f); }
                if (dual) {
                    if (g_mask[r]) {
                        int d = n >> 1;
                        float xr = Cf[(size_t)m * DD + d];
                        float ep = eps[(size_t)r * DD + d];
                        float o = xr * softplusf(v0 + expf(0.5f * v1) * ep);
                        bf h, l;
                        split_bf16(o, h, l);
                        size_t dst = (size_t)g_newpos[r] * DD + d;
                        Ch[dst] = h;
                        Cl[dst] = l;
                    }
                } else if (varw) {
                    float var0 = expf(v0), var1 = expf(v1);
                    float w0 = 1.0f + sqrtf(var0) * eps[(size_t)r * N + n];
                    float w1 = 1.0f + sqrtf(var1) * eps[(size_t)r * N + n + 1];
                    int np = g_newpos[r];
                    if (np >= BB / 2) {
                        size_t jo = (size_t)(np - BB / 2) * N + n;
                        *reinterpret_cast<float2*>(Cf + jo) = make_float2(var0, var1);
                        *reinterpret_cast<float2*>(Cw + jo) = make_float2(w0, w1);
                    }
                    bf h0, l0, h1, l1;
                    split_bf16(w0, h0, l0); split_bf16(w1, h1, l1);
                    *reinterpret_cast<__nv_bfloat162*>(Ch + ro + n) = __nv_bfloat162(h0, h1);
                    *reinterpret_cast<__nv_bfloat162*>(Cl + ro + n) = __nv_bfloat162(l0, l1);
                } else {
                    if (f32s) {
                        *reinterpret_cast<float2*>(Cf + ro + n) = make_float2(v0, v1);
                    }
                    if (hilos) {
                        bf h0, l0, h1, l1;
                        split_bf16(v0, h0, l0); split_bf16(v1, h1, l1);
                        *reinterpret_cast<__nv_bfloat162*>(Ch + ro + n) = __nv_bfloat162(h0, h1);
                        *reinterpret_cast<__nv_bfloat162*>(Cl + ro + n) = __nv_bfloat162(l0, l1);
                    }
                }
            }
        }
    }
}

// ---- elementwise ----
__global__ void copy_kernel(const float* __restrict__ x) {
    int j = blockIdx.y;
    int r = g_perm[j];
    if (g_mask[r]) return;
    int d = (blockIdx.x * 256 + threadIdx.x) * 4;
    float4 v = *reinterpret_cast<const float4*>(x + (size_t)r * DD + d);
    float vv[4] = {v.x, v.y, v.z, v.w};
    bf h[4], l[4];
#pragma unroll
    for (int i = 0; i < 4; ++i) split_bf16(vv[i], h[i], l[i]);
    size_t dst = (size_t)j * DD + d;
    reinterpret_cast<__nv_bfloat162*>(g_cbh + dst)[0] = __nv_bfloat162(h[0], h[1]);
    reinterpret_cast<__nv_bfloat162*>(g_cbh + dst)[1] = __nv_bfloat162(h[2], h[3]);
    reinterpret_cast<__nv_bfloat162*>(g_cbl + dst)[0] = __nv_bfloat162(l[0], l[1]);
    reinterpret_cast<__nv_bfloat162*>(g_cbl + dst)[1] = __nv_bfloat162(l[2], l[3]);
}

// ---- launch ----
static void* sa(const void* s) { void* p = nullptr; cudaGetSymbolAddress(&p, s); return p; }

extern "C" void kernel_launch(void* const* d_in, const int* in_sizes, int n_in,
                              void* d_out, int out_size) {
    const float* x      = (const float*)d_in[0];
    const int*   mm     = (const int*)d_in[1];
    const float* priors = (const float*)d_in[2];
    const float* W1  = (const float*)d_in[3];
    const float* b1  = (const float*)d_in[4];
    const float* W2  = (const float*)d_in[5];
    const float* b2  = (const float*)d_in[6];
    const float* Wr1 = (const float*)d_in[7];
    const float* br1 = (const float*)d_in[8];
    const float* Wlv = (const float*)d_in[9];
    const float* blv = (const float*)d_in[10];
    const float* Wg1 = (const float*)d_in[11];
    const float* bg1 = (const float*)d_in[12];
    const float* Wm  = (const float*)d_in[13];
    const float* bm  = (const float*)d_in[14];
    const float* Wl  = (const float*)d_in[15];
    const float* bl  = (const float*)d_in[16];
    const float* eps_w = (const float*)d_in[17];
    const float* eps_r = (const float*)d_in[18];
    float* out = (float*)d_out;
    float* out_logits = out;
    float* out_w = out + (size_t)BB * OO;
    float* out_var = out_w + (size_t)(BB - BB / 2) * PP;

    cudaFuncSetAttribute(gemm_mma, cudaFuncAttributeMaxDynamicSharedMemorySize, SMEMB);

    bf *Wr1h=(bf*)sa(g_Wr1h), *Wr1l=(bf*)sa(g_Wr1l), *Wlvh=(bf*)sa(g_Wlvh), *Wlvl=(bf*)sa(g_Wlvl);
    bf *Wg1h=(bf*)sa(g_Wg1h), *Wg1l=(bf*)sa(g_Wg1l);
    bf *Wch=(bf*)sa(g_Wch), *Wcl=(bf*)sa(g_Wcl);
    bf *W1h=(bf*)sa(g_W1h), *W1l=(bf*)sa(g_W1l);
    bf *W2h=(bf*)sa(g_W2h), *W2l=(bf*)sa(g_W2l), *pTh=(bf*)sa(g_pTh), *pTl=(bf*)sa(g_pTl);
    bf *xah=(bf*)sa(g_xah), *xal=(bf*)sa(g_xal), *hh=(bf*)sa(g_hh), *hl=(bf*)sa(g_hl);
    bf *wvh=(bf*)sa(g_wvh), *wvl=(bf*)sa(g_wvl), *xrh=(bf*)sa(g_xrh), *xrl=(bf*)sa(g_xrl);
    bf *hrh=(bf*)sa(g_hrh), *hrl=(bf*)sa(g_hrl), *cbh=(bf*)sa(g_cbh), *cbl=(bf*)sa(g_cbl);
    float *pxrecf=(float*)sa(g_xrecf);
    float *pbcat=(float*)sa(g_bcat);

    dim3 blk(512);

    setup_kernel<<<1, 1024>>>(mm);                                  // 0
    convx_kernel<<<dim3(DD/1024, BB), 256>>>(x);                    // 1
    convw_all<<<dim3(16384, 7), 256>>>(Wr1, Wlv, Wg1, Wm, Wl, W1, W2); // 2
    // 3) h = relu(xa @ Wr1^T + br1) -> hi/lo   [launch index 3 = PROFILED]
    gemm_mma<<<dim3(HH/128, BB/128), blk, SMEMB>>>(xah, xal, Wr1h, Wr1l, br1,
        nullptr, hh, hl, nullptr, nullptr, BB, HH, DD, 1|2|8);
    // 4) var/w: direct out_var/out_w + wv hi/lo
    gemm_mma<<<dim3(PP/128, BB/128), blk, SMEMB>>>(hh, hl, Wlvh, Wlvl, blv,
        out_var, wvh, wvl, out_w, eps_w, BB, PP, HH, 1|16);
    convpT_kernel<<<dim3(DD/32, PP/32), dim3(32, 8)>>>(priors);     // 5
    // 6) x_rec = w @ pT^T -> f32 + hi/lo
    gemm_mma<<<dim3(DD/128, BB/128), blk, SMEMB>>>(wvh, wvl, pTh, pTl, nullptr,
        pxrecf, xrh, xrl, nullptr, nullptr, BB, DD, PP, 1|4|8);
    // 7) hr = relu(x_rec @ Wg1^T + bg1)
    gemm_mma<<<dim3(HH/128, BB/128), blk, SMEMB>>>(xrh, xrl, Wg1h, Wg1l, bg1,
        nullptr, hrh, hrl, nullptr, nullptr, BB, HH, DD, 1|2|8);
    concatb_kernel<<<(2*DD)/256, 256>>>(bm, bl);                    // 8
    // 9) fused dual: interleaved [mean|lreg] -> x_reg scatter into cbh/cbl
    gemm_mma<<<dim3((2*DD)/128, BB/128), blk, SMEMB>>>(hrh, hrl, Wch, Wcl, pbcat,
        pxrecf, cbh, cbl, nullptr, eps_r, BB, 2*DD, HH, 1|32);
    copy_kernel<<<dim3(DD/1024, BB), 256>>>(x);                     // 10
    // 11) h1 = relu(comb @ W1^T + b1) (reuse hh/hl)
    gemm_mma<<<dim3(HH/128, BB/128), blk, SMEMB>>>(cbh, cbl, W1h, W1l, b1,
        nullptr, hh, hl, nullptr, nullptr, BB, HH, DD, 2|8);
    // 12) logits
    gemm_mma<<<dim3((OO+127)/128, BB/128), blk, SMEMB>>>(hh, hl, W2h, W2l, b2,
        out_logits, nullptr, nullptr, nullptr, nullptr, BB, OO, HH, 4);
}

// round 11
// speedup vs baseline: 1.2699x; 1.1032x over previous
#include <cuda_runtime.h>
#include <cuda_bf16.h>
#include <cuda_fp16.h>
#include <cstdint>

#define BB 4096
#define DD 4096
#define HH 4096
#define OO 1000
#define PP 2048

typedef __nv_bfloat16 bf;
typedef __half hf;

// ---- device scratch ----
__device__ bf g_Wr1h[(size_t)HH*DD], g_Wr1l[(size_t)HH*DD];
__device__ bf g_Wlvh[(size_t)PP*HH], g_Wlvl[(size_t)PP*HH];
__device__ bf g_Wg1h[(size_t)HH*DD], g_Wg1l[(size_t)HH*DD];
__device__ bf g_Wch [(size_t)2*DD*HH], g_Wcl [(size_t)2*DD*HH]; // Wm/Wl row-interleaved
__device__ bf g_pTh [(size_t)DD*PP], g_pTl [(size_t)DD*PP];
__device__ bf g_xah[(size_t)BB*DD], g_xal[(size_t)BB*DD];
__device__ bf g_hh [(size_t)BB*HH], g_hl [(size_t)BB*HH];
__device__ bf g_wvh[(size_t)BB*PP], g_wvl[(size_t)BB*PP];
__device__ bf g_xrh[(size_t)BB*DD], g_xrl[(size_t)BB*DD];
__device__ bf g_hrh[(size_t)BB*HH], g_hrl[(size_t)BB*HH];
// fp16 tier (logits path)
__device__ hf g_W1fh[(size_t)HH*DD], g_W1fl[(size_t)HH*DD];
__device__ hf g_W2fh[(size_t)OO*HH], g_W2fl[(size_t)OO*HH];
__device__ hf g_cbf [(size_t)BB*DD];
__device__ hf g_h1f [(size_t)BB*HH];
__device__ float g_xrecf[(size_t)BB*DD];
__device__ float g_bcat[2*DD];
__device__ int g_na, g_perm[BB], g_newpos[BB], g_act[BB], g_posinact[BB], g_mask[BB];

// ---- helpers ----
__device__ __forceinline__ float softplusf(float z) {
    return fmaxf(z, 0.0f) + log1pf(expf(-fabsf(z)));
}
__device__ __forceinline__ uint32_t smem_u32(const void* p) {
    uint32_t a;
    asm("{ .reg .u64 t; cvta.to.shared.u64 t, %1; cvt.u32.u64 %0, t; }" : "=r"(a) : "l"(p));
    return a;
}
__device__ __forceinline__ void cpa16(uint32_t dst, const void* src) {
    asm volatile("cp.async.cg.shared.global [%0], [%1], 16;" :: "r"(dst), "l"(src));
}
__device__ __forceinline__ void ldmx4(uint32_t* r, uint32_t a) {
    asm volatile("ldmatrix.sync.aligned.m8n8.x4.shared.b16 {%0,%1,%2,%3}, [%4];"
                 : "=r"(r[0]), "=r"(r[1]), "=r"(r[2]), "=r"(r[3]) : "r"(a));
}
__device__ __forceinline__ void mma16816(float* c, const uint32_t* a, const uint32_t* b) {
    asm("mma.sync.aligned.m16n8k16.row.col.f32.bf16.bf16.f32 "
        "{%0,%1,%2,%3}, {%4,%5,%6,%7}, {%8,%9}, {%0,%1,%2,%3};"
        : "+f"(c[0]), "+f"(c[1]), "+f"(c[2]), "+f"(c[3])
        : "r"(a[0]), "r"(a[1]), "r"(a[2]), "r"(a[3]), "r"(b[0]), "r"(b[1]));
}
__device__ __forceinline__ void mma16816h(float* c, const uint32_t* a, const uint32_t* b) {
    asm("mma.sync.aligned.m16n8k16.row.col.f32.f16.f16.f32 "
        "{%0,%1,%2,%3}, {%4,%5,%6,%7}, {%8,%9}, {%0,%1,%2,%3};"
        : "+f"(c[0]), "+f"(c[1]), "+f"(c[2]), "+f"(c[3])
        : "r"(a[0]), "r"(a[1]), "r"(a[2]), "r"(a[3]), "r"(b[0]), "r"(b[1]));
}
__device__ __forceinline__ void split_bf16(float v, bf& h, bf& l) {
    h = __float2bfloat16_rn(v);
    l = __float2bfloat16_rn(v - __bfloat162float(h));
}
__device__ __forceinline__ void split_f16(float v, hf& h, hf& l) {
    h = __float2half_rn(v);
    l = __float2half_rn(v - __half2float(h));
}

// ---- setup ----
__global__ void setup_kernel(const int* __restrict__ mm) {
    __shared__ int wsum[32];
    __shared__ int sTot[2];
    int tid = threadIdx.x, lane = tid & 31, warp = tid >> 5;
    int base = tid * 4;
    int f[4], incl[4], s = 0;
#pragma unroll
    for (int j = 0; j < 4; ++j) { f[j] = (mm[base + j] % 2 != 0); s += f[j]; incl[j] = s; }
    int v = s;
#pragma unroll
    for (int o = 1; o < 32; o <<= 1) { int u = __shfl_up_sync(~0u, v, o); if (lane >= o) v += u; }
    if (lane == 31) wsum[warp] = v;
    __syncthreads();
    if (warp == 0) {
        int w = wsum[lane];
#pragma unroll
        for (int o = 1; o < 32; o <<= 1) { int u = __shfl_up_sync(~0u, w, o); if (lane >= o) w += u; }
        wsum[lane] = w;
        if (lane == 31) sTot[0] = w;
    }
    __syncthreads();
    int Z = BB - sTot[0];
    int thrExcl = (warp ? wsum[warp - 1] : 0) + (v - s);
    int af[4];
#pragma unroll
    for (int j = 0; j < 4; ++j) {
        int i = base + j;
        int ones = thrExcl + incl[j] - f[j];
        int pos = f[j] ? (Z + ones) : (i - ones);
        g_mask[i] = f[j]; g_newpos[i] = pos; g_perm[pos] = i;
        af[j] = (f[j] || pos >= BB / 2);
    }
    __syncthreads();
    int incl2[4], s2 = 0;
#pragma unroll
    for (int j = 0; j < 4; ++j) { s2 += af[j]; incl2[j] = s2; }
    int v2 = s2;
#pragma unroll
    for (int o = 1; o < 32; o <<= 1) { int u = __shfl_up_sync(~0u, v2, o); if (lane >= o) v2 += u; }
    if (lane == 31) wsum[warp] = v2;
    __syncthreads();
    if (warp == 0) {
        int w = wsum[lane];
#pragma unroll
        for (int o = 1; o < 32; o <<= 1) { int u = __shfl_up_sync(~0u, w, o); if (lane >= o) w += u; }
        wsum[lane] = w;
        if (lane == 31) sTot[1] = w;
    }
    __syncthreads();
    int thrExcl2 = (warp ? wsum[warp - 1] : 0) + (v2 - s2);
#pragma unroll
    for (int j = 0; j < 4; ++j) {
        int i = base + j;
        int ab = thrExcl2 + incl2[j] - af[j];
        if (af[j]) { g_act[ab] = i; g_posinact[i] = ab; } else g_posinact[i] = -1;
    }
    if (tid == 0) g_na = sTot[1];
}

// ---- batched weight conversion (one launch) ----
// segs 0,1,3,5,6: bf16 hi/lo; segs 2 (W1) and 4 (W2): fp16 hi/lo
__global__ void convw_all(const float* __restrict__ Wr1, const float* __restrict__ Wlv,
                          const float* __restrict__ Wg1, const float* __restrict__ Wm,
                          const float* __restrict__ Wl,  const float* __restrict__ W1,
                          const float* __restrict__ W2) {
    int seg = blockIdx.y;
    size_t i = ((size_t)blockIdx.x * 256 + threadIdx.x) * 4;
    const float* src;
    size_t n;
    switch (seg) {
        case 0: src = Wr1; n = (size_t)HH * DD; break;
        case 1: src = Wg1; n = (size_t)HH * DD; break;
        case 2: src = W1;  n = (size_t)HH * DD; break;
        case 3: src = Wlv; n = (size_t)PP * HH; break;
        case 4: src = W2;  n = (size_t)OO * HH; break;
        case 5: src = Wm;  n = (size_t)DD * HH; break;
        default: src = Wl; n = (size_t)DD * HH; break;
    }
    if (i >= n) return;
    float4 v = *reinterpret_cast<const float4*>(src + i);
    float vv[4] = {v.x, v.y, v.z, v.w};
    if (seg == 2 || seg == 4) {
        hf *hi = (seg == 2) ? g_W1fh : g_W2fh;
        hf *lo = (seg == 2) ? g_W1fl : g_W2fl;
        hf h[4], l[4];
#pragma unroll
        for (int j = 0; j < 4; ++j) split_f16(vv[j], h[j], l[j]);
        reinterpret_cast<__half2*>(hi + i)[0] = __half2(h[0], h[1]);
        reinterpret_cast<__half2*>(hi + i)[1] = __half2(h[2], h[3]);
        reinterpret_cast<__half2*>(lo + i)[0] = __half2(l[0], l[1]);
        reinterpret_cast<__half2*>(lo + i)[1] = __half2(l[2], l[3]);
        return;
    }
    bf *hi, *lo;
    size_t o = i;
    switch (seg) {
        case 0: hi = g_Wr1h; lo = g_Wr1l; break;
        case 1: hi = g_Wg1h; lo = g_Wg1l; break;
        case 3: hi = g_Wlvh; lo = g_Wlvl; break;
        default: {   // 5, 6: Wm/Wl interleaved
            hi = g_Wch; lo = g_Wcl;
            size_t row = i / HH, col = i - row * HH;
            o = (row * 2 + (seg - 5)) * HH + col;
        }
    }
    bf h[4], l[4];
#pragma unroll
    for (int j = 0; j < 4; ++j) split_bf16(vv[j], h[j], l[j]);
    reinterpret_cast<__nv_bfloat162*>(hi + o)[0] = __nv_bfloat162(h[0], h[1]);
    reinterpret_cast<__nv_bfloat162*>(hi + o)[1] = __nv_bfloat162(h[2], h[3]);
    reinterpret_cast<__nv_bfloat162*>(lo + o)[0] = __nv_bfloat162(l[0], l[1]);
    reinterpret_cast<__nv_bfloat162*>(lo + o)[1] = __nv_bfloat162(l[2], l[3]);
}

__global__ void convx_kernel(const float* __restrict__ x) {
    int i = blockIdx.y;
    if (i >= g_na) return;
    int r = g_act[i];
    int d = (blockIdx.x * 256 + threadIdx.x) * 4;
    float4 v = *reinterpret_cast<const float4*>(x + (size_t)r * DD + d);
    float vv[4] = {v.x, v.y, v.z, v.w};
    bf h[4], l[4];
#pragma unroll
    for (int j = 0; j < 4; ++j) split_bf16(vv[j], h[j], l[j]);
    size_t o = (size_t)i * DD + d;
    reinterpret_cast<__nv_bfloat162*>(g_xah + o)[0] = __nv_bfloat162(h[0], h[1]);
    reinterpret_cast<__nv_bfloat162*>(g_xah + o)[1] = __nv_bfloat162(h[2], h[3]);
    reinterpret_cast<__nv_bfloat162*>(g_xal + o)[0] = __nv_bfloat162(l[0], l[1]);
    reinterpret_cast<__nv_bfloat162*>(g_xal + o)[1] = __nv_bfloat162(l[2], l[3]);
}
__global__ void convpT_kernel(const float* __restrict__ P) {
    __shared__ float tile[32][33];
    int d0 = blockIdx.x * 32, p0 = blockIdx.y * 32;
    int tx = threadIdx.x, ty = threadIdx.y;
#pragma unroll
    for (int i = 0; i < 4; ++i)
        tile[ty + i * 8][tx] = P[(size_t)(p0 + ty + i * 8) * DD + d0 + tx];
    __syncthreads();
#pragma unroll
    for (int i = 0; i < 4; ++i) {
        bf h, l;
        split_bf16(tile[tx][ty + i * 8], h, l);
        size_t o = (size_t)(d0 + ty + i * 8) * PP + p0 + tx;
        g_pTh[o] = h; g_pTl[o] = l;
    }
}
__global__ void concatb_kernel(const float* __restrict__ a, const float* __restrict__ b) {
    int i = blockIdx.x * 256 + threadIdx.x;   // interleaved: even=bm, odd=bl
    g_bcat[i] = (i & 1) ? b[i >> 1] : a[i >> 1];
}

// ================= bf16 3-product GEMM (VAE branch) =================
// 128x128 CTA tile, BK=64, 3-stage, 512 threads, 1 CTA/SM
// flags: 1=Meff from g_na, 2=relu, 4=f32 out, 8=hi/lo out, 16=var/w, 32=xreg-fused dual(fp16 comb out)
#define ROWB 144
#define TILE_B (128 * ROWB)
#define STAGE_B (4 * TILE_B)
#define NSTG 3
#define SMEMB (NSTG * STAGE_B + 512)

__global__ void __launch_bounds__(512, 1)
gemm_mma(const bf* __restrict__ Ah, const bf* __restrict__ Al,
         const bf* __restrict__ Bh, const bf* __restrict__ Bl,
         const float* __restrict__ bias, float* __restrict__ Cf,
         bf* __restrict__ Ch, bf* __restrict__ Cl,
         float* __restrict__ Cw, const float* __restrict__ eps,
         int M, int N, int K, int flags)
{
    int Meff = (flags & 1) ? g_na : M;
    int mT = blockIdx.y * 128;
    if (mT >= Meff) return;
    int nT = blockIdx.x * 128;

    extern __shared__ char sm[];
    uint32_t sb = smem_u32(sm);
    float* biasS = reinterpret_cast<float*>(sm + NSTG * STAGE_B);

    int tid = threadIdx.x, wid = tid >> 5, lane = tid & 31;
    int wm = wid & 3, wn = wid >> 2;

    if (tid < 128) {
        int n = nT + tid;
        biasS[tid] = (bias && n < N) ? bias[n] : 0.0f;
    }

    uint32_t aBase = (wm * 32 + (lane & 15)) * ROWB + ((lane >> 4) & 1) * 16;
    uint32_t bBase = 2 * TILE_B + (wn * 32 + ((lane >> 4) & 1) * 8 + (lane & 7)) * ROWB +
                     ((lane >> 3) & 1) * 16;

    float acc[2][4][4];
#pragma unroll
    for (int a = 0; a < 2; ++a)
#pragma unroll
        for (int b = 0; b < 4; ++b)
#pragma unroll
            for (int c = 0; c < 4; ++c) acc[a][b][c] = 0.0f;

    int nK = K / 64;

#define LOAD_STAGE(s, k0)                                                        \
    {                                                                            \
        uint32_t st = sb + (s) * STAGE_B;                                        \
        _Pragma("unroll")                                                        \
        for (int i = 0; i < 2; ++i) {                                            \
            int idx = i * 512 + tid;                                             \
            int r = idx >> 3, c16 = idx & 7;                                     \
            int rg = mT + r; rg = rg < Meff ? rg : Meff - 1;                     \
            size_t go = (size_t)rg * K + (k0) + c16 * 8;                         \
            uint32_t off = r * ROWB + c16 * 16;                                  \
            cpa16(st + off, Ah + go);                                            \
            cpa16(st + TILE_B + off, Al + go);                                   \
        }                                                                        \
        _Pragma("unroll")                                                        \
        for (int i = 0; i < 2; ++i) {                                            \
            int idx = i * 512 + tid;                                             \
            int r = idx >> 3, c16 = idx & 7;                                     \
            int rg = nT + r; rg = rg < N ? rg : N - 1;                           \
            size_t go = (size_t)rg * K + (k0) + c16 * 8;                         \
            uint32_t off = r * ROWB + c16 * 16;                                  \
            cpa16(st + 2 * TILE_B + off, Bh + go);                               \
            cpa16(st + 3 * TILE_B + off, Bl + go);                               \
        }                                                                        \
    }

#define LOAD_FRAGS(st, kh, AH, AL, BH, BL)                                       \
    {                                                                            \
        uint32_t ab = (st) + aBase + (kh) * 32;                                  \
        _Pragma("unroll")                                                        \
        for (int ma = 0; ma < 2; ++ma) {                                         \
            ldmx4(AH[ma], ab + ma * 16 * ROWB);                                  \
            ldmx4(AL[ma], ab + ma * 16 * ROWB + TILE_B);                         \
        }                                                                        \
        uint32_t bb = (st) + bBase + (kh) * 32;                                  \
        _Pragma("unroll")                                                        \
        for (int p = 0; p < 2; ++p) {                                            \
            uint32_t t[4];                                                       \
            ldmx4(t, bb + p * 16 * ROWB);                                        \
            BH[2*p][0] = t[0]; BH[2*p][1] = t[1];                                \
            BH[2*p+1][0] = t[2]; BH[2*p+1][1] = t[3];                            \
            ldmx4(t, bb + p * 16 * ROWB + TILE_B);                               \
            BL[2*p][0] = t[0]; BL[2*p][1] = t[1];                                \
            BL[2*p+1][0] = t[2]; BL[2*p+1][1] = t[3];                            \
        }                                                                        \
    }

#define MMA_BLOCK(AH, AL, BH, BL)                                                \
    {                                                                            \
        _Pragma("unroll")                                                        \
        for (int ma = 0; ma < 2; ++ma)                                           \
            _Pragma("unroll")                                                    \
            for (int na = 0; na < 4; ++na) mma16816(acc[ma][na], AH[ma], BH[na]);\
        _Pragma("unroll")                                                        \
        for (int ma = 0; ma < 2; ++ma)                                           \
            _Pragma("unroll")                                                    \
            for (int na = 0; na < 4; ++na) mma16816(acc[ma][na], AH[ma], BL[na]);\
        _Pragma("unroll")                                                        \
        for (int ma = 0; ma < 2; ++ma)                                           \
            _Pragma("unroll")                                                    \
            for (int na = 0; na < 4; ++na) mma16816(acc[ma][na], AL[ma], BH[na]);\
    }

    LOAD_STAGE(0, 0);
    asm volatile("cp.async.commit_group;");
    LOAD_STAGE(1, 64);
    asm volatile("cp.async.commit_group;");

    uint32_t a0h[2][4], a0l[2][4], b0h[4][2], b0l[4][2];
    uint32_t a1h[2][4], a1l[2][4], b1h[4][2], b1l[4][2];

    asm volatile("cp.async.wait_group 1;");
    __syncthreads();
    LOAD_FRAGS(sb, 0, a0h, a0l, b0h, b0l);

    int s_cur = 0;
#pragma unroll 1
    for (int it = 0; it < nK; ++it) {
        uint32_t st = sb + s_cur * STAGE_B;
        LOAD_FRAGS(st, 1, a1h, a1l, b1h, b1l);
        MMA_BLOCK(a0h, a0l, b0h, b0l);
        LOAD_FRAGS(st, 2, a0h, a0l, b0h, b0l);
        MMA_BLOCK(a1h, a1l, b1h, b1l);
        LOAD_FRAGS(st, 3, a1h, a1l, b1h, b1l);
        MMA_BLOCK(a0h, a0l, b0h, b0l);
        int ps = it + 2;
        int s_tgt = s_cur + 2 >= NSTG ? s_cur + 2 - NSTG : s_cur + 2;
        if (ps < nK) LOAD_STAGE(s_tgt, ps * 64);
        asm volatile("cp.async.commit_group;");
        asm volatile("cp.async.wait_group 1;");
        __syncthreads();
        if (it + 1 < nK) {
            int s_n = s_cur + 1 == NSTG ? 0 : s_cur + 1;
            uint32_t st2 = sb + s_n * STAGE_B;
            LOAD_FRAGS(st2, 0, a0h, a0l, b0h, b0l);
        }
        MMA_BLOCK(a1h, a1l, b1h, b1l);
        s_cur = s_cur + 1 == NSTG ? 0 : s_cur + 1;
    }

    // ---- epilogue ----
    bool relu = flags & 2, f32s = flags & 4, hilos = flags & 8;
    bool varw = flags & 16, dual = flags & 32;
#pragma unroll
    for (int ma = 0; ma < 2; ++ma) {
#pragma unroll
        for (int rs = 0; rs < 2; ++rs) {
            int m = mT + wm * 32 + ma * 16 + (lane >> 2) + rs * 8;
            if (m >= Meff) continue;
            size_t ro = (size_t)m * N;
            int r = (varw || dual) ? g_act[m] : 0;
#pragma unroll
            for (int na = 0; na < 4; ++na) {
                int nc = wn * 32 + na * 8 + (lane & 3) * 2;
                int n = nT + nc;
                if (n >= N) continue;
                float v0 = acc[ma][na][rs * 2 + 0] + biasS[nc];
                float v1 = acc[ma][na][rs * 2 + 1] + biasS[nc + 1];
                if (relu) { v0 = fmaxf(v0, 0.0f); v1 = fmaxf(v1, 0.0f); }
                if (dual) {
                    // interleaved Wm/Wl: v0 = mean_d, v1 = lreg_d, d = n/2
                    if (g_mask[r]) {
                        int d = n >> 1;
                        float xr = Cf[(size_t)m * DD + d];
                        float ep = eps[(size_t)r * DD + d];
                        float o = xr * softplusf(v0 + expf(0.5f * v1) * ep);
                        size_t dst = (size_t)g_newpos[r] * DD + d;
                        reinterpret_cast<hf*>(Ch)[dst] = __float2half_rn(o);
                    }
                } else if (varw) {
                    float var0 = expf(v0), var1 = expf(v1);
                    float w0 = 1.0f + sqrtf(var0) * eps[(size_t)r * N + n];
                    float w1 = 1.0f + sqrtf(var1) * eps[(size_t)r * N + n + 1];
                    int np = g_newpos[r];
                    if (np >= BB / 2) {
                        size_t jo = (size_t)(np - BB / 2) * N + n;
                        *reinterpret_cast<float2*>(Cf + jo) = make_float2(var0, var1);
                        *reinterpret_cast<float2*>(Cw + jo) = make_float2(w0, w1);
                    }
                    bf h0, l0, h1, l1;
                    split_bf16(w0, h0, l0); split_bf16(w1, h1, l1);
                    *reinterpret_cast<__nv_bfloat162*>(Ch + ro + n) = __nv_bfloat162(h0, h1);
                    *reinterpret_cast<__nv_bfloat162*>(Cl + ro + n) = __nv_bfloat162(l0, l1);
                } else {
                    if (f32s) {
                        *reinterpret_cast<float2*>(Cf + ro + n) = make_float2(v0, v1);
                    }
                    if (hilos) {
                        bf h0, l0, h1, l1;
                        split_bf16(v0, h0, l0); split_bf16(v1, h1, l1);
                        *reinterpret_cast<__nv_bfloat162*>(Ch + ro + n) = __nv_bfloat162(h0, h1);
                        *reinterpret_cast<__nv_bfloat162*>(Cl + ro + n) = __nv_bfloat162(l0, l1);
                    }
                }
            }
        }
    }
}

// ================= fp16 2-product GEMM (logits path) =================
// A plain fp16, B fp16 hi/lo. C = A@(Bh+Bl)^T. Same tiling/pipeline.
// flags: 2=relu + fp16 out (Chf), 4=f32 out (Cf). bias always added.
#define TILE_F (128 * ROWB)
#define STAGE_F (3 * TILE_F)     // A, Bh, Bl
#define SMEMF (NSTG * STAGE_F + 512)

__global__ void __launch_bounds__(512, 1)
gemm_f16(const hf* __restrict__ A, const hf* __restrict__ Bh, const hf* __restrict__ Bl,
         const float* __restrict__ bias, float* __restrict__ Cf, hf* __restrict__ Chf,
         int M, int N, int K, int flags)
{
    int mT = blockIdx.y * 128;
    int nT = blockIdx.x * 128;

    extern __shared__ char sm[];
    uint32_t sb = smem_u32(sm);
    float* biasS = reinterpret_cast<float*>(sm + NSTG * STAGE_F);

    int tid = threadIdx.x, wid = tid >> 5, lane = tid & 31;
    int wm = wid & 3, wn = wid >> 2;

    if (tid < 128) {
        int n = nT + tid;
        biasS[tid] = (bias && n < N) ? bias[n] : 0.0f;
    }

    uint32_t aBase = (wm * 32 + (lane & 15)) * ROWB + ((lane >> 4) & 1) * 16;
    uint32_t bBase = TILE_F + (wn * 32 + ((lane >> 4) & 1) * 8 + (lane & 7)) * ROWB +
                     ((lane >> 3) & 1) * 16;

    float acc[2][4][4];
#pragma unroll
    for (int a = 0; a < 2; ++a)
#pragma unroll
        for (int b = 0; b < 4; ++b)
#pragma unroll
            for (int c = 0; c < 4; ++c) acc[a][b][c] = 0.0f;

    int nK = K / 64;

#define LOAD_STAGE_F(s, k0)                                                      \
    {                                                                            \
        uint32_t st = sb + (s) * STAGE_F;                                        \
        _Pragma("unroll")                                                        \
        for (int i = 0; i < 2; ++i) {                                            \
            int idx = i * 512 + tid;                                             \
            int r = idx >> 3, c16 = idx & 7;                                     \
            size_t go = (size_t)(mT + r) * K + (k0) + c16 * 8;                   \
            cpa16(st + r * ROWB + c16 * 16, A + go);                             \
        }                                                                        \
        _Pragma("unroll")                                                        \
        for (int i = 0; i < 2; ++i) {                                            \
            int idx = i * 512 + tid;                                             \
            int r = idx >> 3, c16 = idx & 7;                                     \
            int rg = nT + r; rg = rg < N ? rg : N - 1;                           \
            size_t go = (size_t)rg * K + (k0) + c16 * 8;                         \
            uint32_t off = r * ROWB + c16 * 16;                                  \
            cpa16(st + TILE_F + off, Bh + go);                                   \
            cpa16(st + 2 * TILE_F + off, Bl + go);                               \
        }                                                                        \
    }

#define LOAD_FRAGS_F(st, kh, AR, BH, BL)                                         \
    {                                                                            \
        uint32_t ab = (st) + aBase + (kh) * 32;                                  \
        _Pragma("unroll")                                                        \
        for (int ma = 0; ma < 2; ++ma) ldmx4(AR[ma], ab + ma * 16 * ROWB);       \
        uint32_t bb = (st) + bBase + (kh) * 32;                                  \
        _Pragma("unroll")                                                        \
        for (int p = 0; p < 2; ++p) {                                            \
            uint32_t t[4];                                                       \
            ldmx4(t, bb + p * 16 * ROWB);                                        \
            BH[2*p][0] = t[0]; BH[2*p][1] = t[1];                                \
            BH[2*p+1][0] = t[2]; BH[2*p+1][1] = t[3];                            \
            ldmx4(t, bb + p * 16 * ROWB + TILE_F);                               \
            BL[2*p][0] = t[0]; BL[2*p][1] = t[1];                                \
            BL[2*p+1][0] = t[2]; BL[2*p+1][1] = t[3];                            \
        }                                                                        \
    }

#define MMA_BLOCK_F(AR, BH, BL)                                                  \
    {                                                                            \
        _Pragma("unroll")                                                        \
        for (int ma = 0; ma < 2; ++ma)                                           \
            _Pragma("unroll")                                                    \
            for (int na = 0; na < 4; ++na) mma16816h(acc[ma][na], AR[ma], BH[na]);\
        _Pragma("unroll")                                                        \
        for (int ma = 0; ma < 2; ++ma)                                           \
            _Pragma("unroll")                                                    \
            for (int na = 0; na < 4; ++na) mma16816h(acc[ma][na], AR[ma], BL[na]);\
    }

    LOAD_STAGE_F(0, 0);
    asm volatile("cp.async.commit_group;");
    LOAD_STAGE_F(1, 64);
    asm volatile("cp.async.commit_group;");

    uint32_t a0[2][4], b0h[4][2], b0l[4][2];
    uint32_t a1[2][4], b1h[4][2], b1l[4][2];

    asm volatile("cp.async.wait_group 1;");
    __syncthreads();
    LOAD_FRAGS_F(sb, 0, a0, b0h, b0l);

    int s_cur = 0;
#pragma unroll 1
    for (int it = 0; it < nK; ++it) {
        uint32_t st = sb + s_cur * STAGE_F;
        LOAD_FRAGS_F(st, 1, a1, b1h, b1l);
        MMA_BLOCK_F(a0, b0h, b0l);
        LOAD_FRAGS_F(st, 2, a0, b0h, b0l);
        MMA_BLOCK_F(a1, b1h, b1l);
        LOAD_FRAGS_F(st, 3, a1, b1h, b1l);
        MMA_BLOCK_F(a0, b0h, b0l);
        int ps = it + 2;
        int s_tgt = s_cur + 2 >= NSTG ? s_cur + 2 - NSTG : s_cur + 2;
        if (ps < nK) LOAD_STAGE_F(s_tgt, ps * 64);
        asm volatile("cp.async.commit_group;");
        asm volatile("cp.async.wait_group 1;");
        __syncthreads();
        if (it + 1 < nK) {
            int s_n = s_cur + 1 == NSTG ? 0 : s_cur + 1;
            uint32_t st2 = sb + s_n * STAGE_F;
            LOAD_FRAGS_F(st2, 0, a0, b0h, b0l);
        }
        MMA_BLOCK_F(a1, b1h, b1l);
        s_cur = s_cur + 1 == NSTG ? 0 : s_cur + 1;
    }

    bool relu = flags & 2, f32s = flags & 4;
#pragma unroll
    for (int ma = 0; ma < 2; ++ma) {
#pragma unroll
        for (int rs = 0; rs < 2; ++rs) {
            int m = mT + wm * 32 + ma * 16 + (lane >> 2) + rs * 8;
            size_t ro = (size_t)m * N;
#pragma unroll
            for (int na = 0; na < 4; ++na) {
                int nc = wn * 32 + na * 8 + (lane & 3) * 2;
                int n = nT + nc;
                if (n >= N) continue;
                float v0 = acc[ma][na][rs * 2 + 0] + biasS[nc];
                float v1 = acc[ma][na][rs * 2 + 1] + biasS[nc + 1];
                if (relu) {
                    v0 = fmaxf(v0, 0.0f); v1 = fmaxf(v1, 0.0f);
                    *reinterpret_cast<__half2*>(Chf + ro + n) =
                        __floats2half2_rn(v0, v1);
                }
                if (f32s) {
                    *reinterpret_cast<float2*>(Cf + ro + n) = make_float2(v0, v1);
                }
            }
        }
    }
}

// ---- elementwise ----
__global__ void copy_kernel(const float* __restrict__ x) {
    int j = blockIdx.y;
    int r = g_perm[j];
    if (g_mask[r]) return;
    int d = (blockIdx.x * 256 + threadIdx.x) * 4;
    float4 v = *reinterpret_cast<const float4*>(x + (size_t)r * DD + d);
    size_t dst = (size_t)j * DD + d;
    reinterpret_cast<__half2*>(g_cbf + dst)[0] = __floats2half2_rn(v.x, v.y);
    reinterpret_cast<__half2*>(g_cbf + dst)[1] = __floats2half2_rn(v.z, v.w);
}

// ---- launch ----
static void* sa(const void* s) { void* p = nullptr; cudaGetSymbolAddress(&p, s); return p; }

extern "C" void kernel_launch(void* const* d_in, const int* in_sizes, int n_in,
                              void* d_out, int out_size) {
    const float* x      = (const float*)d_in[0];
    const int*   mm     = (const int*)d_in[1];
    const float* priors = (const float*)d_in[2];
    const float* W1  = (const float*)d_in[3];
    const float* b1  = (const float*)d_in[4];
    const float* W2  = (const float*)d_in[5];
    const float* b2  = (const float*)d_in[6];
    const float* Wr1 = (const float*)d_in[7];
    const float* br1 = (const float*)d_in[8];
    const float* Wlv = (const float*)d_in[9];
    const float* blv = (const float*)d_in[10];
    const float* Wg1 = (const float*)d_in[11];
    const float* bg1 = (const float*)d_in[12];
    const float* Wm  = (const float*)d_in[13];
    const float* bm  = (const float*)d_in[14];
    const float* Wl  = (const float*)d_in[15];
    const float* bl  = (const float*)d_in[16];
    const float* eps_w = (const float*)d_in[17];
    const float* eps_r = (const float*)d_in[18];
    float* out = (float*)d_out;
    float* out_logits = out;
    float* out_w = out + (size_t)BB * OO;
    float* out_var = out_w + (size_t)(BB - BB / 2) * PP;

    cudaFuncSetAttribute(gemm_mma, cudaFuncAttributeMaxDynamicSharedMemorySize, SMEMB);
    cudaFuncSetAttribute(gemm_f16, cudaFuncAttributeMaxDynamicSharedMemorySize, SMEMF);

    bf *Wr1h=(bf*)sa(g_Wr1h), *Wr1l=(bf*)sa(g_Wr1l), *Wlvh=(bf*)sa(g_Wlvh), *Wlvl=(bf*)sa(g_Wlvl);
    bf *Wg1h=(bf*)sa(g_Wg1h), *Wg1l=(bf*)sa(g_Wg1l);
    bf *Wch=(bf*)sa(g_Wch), *Wcl=(bf*)sa(g_Wcl);
    bf *pTh=(bf*)sa(g_pTh), *pTl=(bf*)sa(g_pTl);
    bf *xah=(bf*)sa(g_xah), *xal=(bf*)sa(g_xal), *hh=(bf*)sa(g_hh), *hl=(bf*)sa(g_hl);
    bf *wvh=(bf*)sa(g_wvh), *wvl=(bf*)sa(g_wvl), *xrh=(bf*)sa(g_xrh), *xrl=(bf*)sa(g_xrl);
    bf *hrh=(bf*)sa(g_hrh), *hrl=(bf*)sa(g_hrl);
    hf *W1fh=(hf*)sa(g_W1fh), *W1fl=(hf*)sa(g_W1fl);
    hf *W2fh=(hf*)sa(g_W2fh), *W2fl=(hf*)sa(g_W2fl);
    hf *cbf=(hf*)sa(g_cbf), *h1f=(hf*)sa(g_h1f);
    float *pxrecf=(float*)sa(g_xrecf);
    float *pbcat=(float*)sa(g_bcat);

    dim3 blk(512);

    setup_kernel<<<1, 1024>>>(mm);                                  // 0
    convx_kernel<<<dim3(DD/1024, BB), 256>>>(x);                    // 1
    convw_all<<<dim3(16384, 7), 256>>>(Wr1, Wlv, Wg1, Wm, Wl, W1, W2); // 2
    // 3) h = relu(xa @ Wr1^T + br1) -> hi/lo   [launch index 3 = PROFILED]
    gemm_mma<<<dim3(HH/128, BB/128), blk, SMEMB>>>(xah, xal, Wr1h, Wr1l, br1,
        nullptr, hh, hl, nullptr, nullptr, BB, HH, DD, 1|2|8);
    // 4) var/w: direct out_var/out_w + wv hi/lo
    gemm_mma<<<dim3(PP/128, BB/128), blk, SMEMB>>>(hh, hl, Wlvh, Wlvl, blv,
        out_var, wvh, wvl, out_w, eps_w, BB, PP, HH, 1|16);
    convpT_kernel<<<dim3(DD/32, PP/32), dim3(32, 8)>>>(priors);     // 5
    // 6) x_rec = w @ pT^T -> f32 + hi/lo
    gemm_mma<<<dim3(DD/128, BB/128), blk, SMEMB>>>(wvh, wvl, pTh, pTl, nullptr,
        pxrecf, xrh, xrl, nullptr, nullptr, BB, DD, PP, 1|4|8);
    // 7) hr = relu(x_rec @ Wg1^T + bg1)
    gemm_mma<<<dim3(HH/128, BB/128), blk, SMEMB>>>(xrh, xrl, Wg1h, Wg1l, bg1,
        nullptr, hrh, hrl, nullptr, nullptr, BB, HH, DD, 1|2|8);
    concatb_kernel<<<(2*DD)/256, 256>>>(bm, bl);                    // 8
    // 9) fused dual: interleaved [mean|lreg] -> x_reg scatter into cbf (fp16)
    gemm_mma<<<dim3((2*DD)/128, BB/128), blk, SMEMB>>>(hrh, hrl, Wch, Wcl, pbcat,
        pxrecf, (bf*)cbf, nullptr, nullptr, eps_r, BB, 2*DD, HH, 1|32);
    copy_kernel<<<dim3(DD/1024, BB), 256>>>(x);                     // 10
    // 11) h1 = relu(comb @ W1^T + b1)  [fp16 2-product]
    gemm_f16<<<dim3(HH/128, BB/128), blk, SMEMF>>>(cbf, W1fh, W1fl, b1,
        nullptr, h1f, BB, HH, DD, 2);
    // 12) logits = h1 @ W2^T + b2      [fp16 2-product]
    gemm_f16<<<dim3((OO+127)/128, BB/128), blk, SMEMF>>>(h1f, W2fh, W2fl, b2,
        out_logits, nullptr, BB, OO, HH, 4);
}

// round 13
// speedup vs baseline: 1.5480x; 1.2190x over previous
#include <cuda_runtime.h>
#include <cuda_bf16.h>
#include <cuda_fp16.h>
#include <cstdint>

#define BB 4096
#define DD 4096
#define HH 4096
#define OO 1000
#define PP 2048

typedef __nv_bfloat16 bf;
typedef __half hf;

// ---- device scratch ----
// bf16 hi/lo tier (VAE outputs path: G1, G2)
__device__ bf g_Wr1h[(size_t)HH*DD], g_Wr1l[(size_t)HH*DD];
__device__ bf g_Wlvh[(size_t)PP*HH], g_Wlvl[(size_t)PP*HH];
__device__ bf g_xah[(size_t)BB*DD], g_xal[(size_t)BB*DD];
__device__ bf g_hh [(size_t)BB*HH], g_hl [(size_t)BB*HH];
// fp16 tier (logits path: G3, G4, G9, G11, G12)
__device__ hf g_Wg1fh[(size_t)HH*DD], g_Wg1fl[(size_t)HH*DD];
__device__ hf g_Wcfh [(size_t)2*DD*HH], g_Wcfl [(size_t)2*DD*HH]; // Wm/Wl row-interleaved
__device__ hf g_W1fh[(size_t)HH*DD], g_W1fl[(size_t)HH*DD];
__device__ hf g_W2fh[(size_t)OO*HH], g_W2fl[(size_t)OO*HH];
__device__ hf g_pTfh[(size_t)DD*PP], g_pTfl[(size_t)DD*PP];
__device__ hf g_wvf [(size_t)BB*PP];
__device__ hf g_xrf [(size_t)BB*DD];
__device__ hf g_hrf [(size_t)BB*HH];
__device__ hf g_cbf [(size_t)BB*DD];
__device__ hf g_h1f [(size_t)BB*HH];
__device__ float g_xrecf[(size_t)BB*DD];
__device__ float g_bcat[2*DD];
__device__ int g_na, g_perm[BB], g_newpos[BB], g_act[BB], g_posinact[BB], g_mask[BB];

// ---- helpers ----
__device__ __forceinline__ float softplusf(float z) {
    return fmaxf(z, 0.0f) + log1pf(expf(-fabsf(z)));
}
__device__ __forceinline__ uint32_t smem_u32(const void* p) {
    uint32_t a;
    asm("{ .reg .u64 t; cvta.to.shared.u64 t, %1; cvt.u32.u64 %0, t; }" : "=r"(a) : "l"(p));
    return a;
}
__device__ __forceinline__ void cpa16(uint32_t dst, const void* src) {
    asm volatile("cp.async.cg.shared.global [%0], [%1], 16;" :: "r"(dst), "l"(src));
}
__device__ __forceinline__ void ldmx4(uint32_t* r, uint32_t a) {
    asm volatile("ldmatrix.sync.aligned.m8n8.x4.shared.b16 {%0,%1,%2,%3}, [%4];"
                 : "=r"(r[0]), "=r"(r[1]), "=r"(r[2]), "=r"(r[3]) : "r"(a));
}
__device__ __forceinline__ void mma16816(float* c, const uint32_t* a, const uint32_t* b) {
    asm("mma.sync.aligned.m16n8k16.row.col.f32.bf16.bf16.f32 "
        "{%0,%1,%2,%3}, {%4,%5,%6,%7}, {%8,%9}, {%0,%1,%2,%3};"
        : "+f"(c[0]), "+f"(c[1]), "+f"(c[2]), "+f"(c[3])
        : "r"(a[0]), "r"(a[1]), "r"(a[2]), "r"(a[3]), "r"(b[0]), "r"(b[1]));
}
__device__ __forceinline__ void mma16816h(float* c, const uint32_t* a, const uint32_t* b) {
    asm("mma.sync.aligned.m16n8k16.row.col.f32.f16.f16.f32 "
        "{%0,%1,%2,%3}, {%4,%5,%6,%7}, {%8,%9}, {%0,%1,%2,%3};"
        : "+f"(c[0]), "+f"(c[1]), "+f"(c[2]), "+f"(c[3])
        : "r"(a[0]), "r"(a[1]), "r"(a[2]), "r"(a[3]), "r"(b[0]), "r"(b[1]));
}
__device__ __forceinline__ void split_bf16(float v, bf& h, bf& l) {
    h = __float2bfloat16_rn(v);
    l = __float2bfloat16_rn(v - __bfloat162float(h));
}
__device__ __forceinline__ void split_f16(float v, hf& h, hf& l) {
    h = __float2half_rn(v);
    l = __float2half_rn(v - __half2float(h));
}

// ---- setup ----
__global__ void setup_kernel(const int* __restrict__ mm) {
    __shared__ int wsum[32];
    __shared__ int sTot[2];
    int tid = threadIdx.x, lane = tid & 31, warp = tid >> 5;
    int base = tid * 4;
    int f[4], incl[4], s = 0;
#pragma unroll
    for (int j = 0; j < 4; ++j) { f[j] = (mm[base + j] % 2 != 0); s += f[j]; incl[j] = s; }
    int v = s;
#pragma unroll
    for (int o = 1; o < 32; o <<= 1) { int u = __shfl_up_sync(~0u, v, o); if (lane >= o) v += u; }
    if (lane == 31) wsum[warp] = v;
    __syncthreads();
    if (warp == 0) {
        int w = wsum[lane];
#pragma unroll
        for (int o = 1; o < 32; o <<= 1) { int u = __shfl_up_sync(~0u, w, o); if (lane >= o) w += u; }
        wsum[lane] = w;
        if (lane == 31) sTot[0] = w;
    }
    __syncthreads();
    int Z = BB - sTot[0];
    int thrExcl = (warp ? wsum[warp - 1] : 0) + (v - s);
    int af[4];
#pragma unroll
    for (int j = 0; j < 4; ++j) {
        int i = base + j;
        int ones = thrExcl + incl[j] - f[j];
        int pos = f[j] ? (Z + ones) : (i - ones);
        g_mask[i] = f[j]; g_newpos[i] = pos; g_perm[pos] = i;
        af[j] = (f[j] || pos >= BB / 2);
    }
    __syncthreads();
    int incl2[4], s2 = 0;
#pragma unroll
    for (int j = 0; j < 4; ++j) { s2 += af[j]; incl2[j] = s2; }
    int v2 = s2;
#pragma unroll
    for (int o = 1; o < 32; o <<= 1) { int u = __shfl_up_sync(~0u, v2, o); if (lane >= o) v2 += u; }
    if (lane == 31) wsum[warp] = v2;
    __syncthreads();
    if (warp == 0) {
        int w = wsum[lane];
#pragma unroll
        for (int o = 1; o < 32; o <<= 1) { int u = __shfl_up_sync(~0u, w, o); if (lane >= o) w += u; }
        wsum[lane] = w;
        if (lane == 31) sTot[1] = w;
    }
    __syncthreads();
    int thrExcl2 = (warp ? wsum[warp - 1] : 0) + (v2 - s2);
#pragma unroll
    for (int j = 0; j < 4; ++j) {
        int i = base + j;
        int ab = thrExcl2 + incl2[j] - af[j];
        if (af[j]) { g_act[ab] = i; g_posinact[i] = ab; } else g_posinact[i] = -1;
    }
    if (tid == 0) g_na = sTot[1];
}

// ---- batched weight conversion ----
// seg 0: Wr1 bf16; seg 3: Wlv bf16; seg 1: Wg1 fp16; seg 2: W1 fp16;
// seg 4: W2 fp16; segs 5,6: Wm/Wl fp16 interleaved
__global__ void convw_all(const float* __restrict__ Wr1, const float* __restrict__ Wlv,
                          const float* __restrict__ Wg1, const float* __restrict__ Wm,
                          const float* __restrict__ Wl,  const float* __restrict__ W1,
                          const float* __restrict__ W2) {
    int seg = blockIdx.y;
    size_t i = ((size_t)blockIdx.x * 256 + threadIdx.x) * 4;
    const float* src;
    size_t n;
    switch (seg) {
        case 0: src = Wr1; n = (size_t)HH * DD; break;
        case 1: src = Wg1; n = (size_t)HH * DD; break;
        case 2: src = W1;  n = (size_t)HH * DD; break;
        case 3: src = Wlv; n = (size_t)PP * HH; break;
        case 4: src = W2;  n = (size_t)OO * HH; break;
        case 5: src = Wm;  n = (size_t)DD * HH; break;
        default: src = Wl; n = (size_t)DD * HH; break;
    }
    if (i >= n) return;
    float4 v = *reinterpret_cast<const float4*>(src + i);
    float vv[4] = {v.x, v.y, v.z, v.w};
    if (seg == 0 || seg == 3) {
        bf *hi = (seg == 0) ? g_Wr1h : g_Wlvh;
        bf *lo = (seg == 0) ? g_Wr1l : g_Wlvl;
        bf h[4], l[4];
#pragma unroll
        for (int j = 0; j < 4; ++j) split_bf16(vv[j], h[j], l[j]);
        reinterpret_cast<__nv_bfloat162*>(hi + i)[0] = __nv_bfloat162(h[0], h[1]);
        reinterpret_cast<__nv_bfloat162*>(hi + i)[1] = __nv_bfloat162(h[2], h[3]);
        reinterpret_cast<__nv_bfloat162*>(lo + i)[0] = __nv_bfloat162(l[0], l[1]);
        reinterpret_cast<__nv_bfloat162*>(lo + i)[1] = __nv_bfloat162(l[2], l[3]);
        return;
    }
    hf *hi, *lo;
    size_t o = i;
    switch (seg) {
        case 1: hi = g_Wg1fh; lo = g_Wg1fl; break;
        case 2: hi = g_W1fh;  lo = g_W1fl;  break;
        case 4: hi = g_W2fh;  lo = g_W2fl;  break;
        default: {   // 5, 6: Wm/Wl interleaved (even rows = Wm, odd = Wl)
            hi = g_Wcfh; lo = g_Wcfl;
            size_t row = i / HH, col = i - row * HH;
            o = (row * 2 + (seg - 5)) * HH + col;
        }
    }
    hf h[4], l[4];
#pragma unroll
    for (int j = 0; j < 4; ++j) split_f16(vv[j], h[j], l[j]);
    reinterpret_cast<__half2*>(hi + o)[0] = __half2(h[0], h[1]);
    reinterpret_cast<__half2*>(hi + o)[1] = __half2(h[2], h[3]);
    reinterpret_cast<__half2*>(lo + o)[0] = __half2(l[0], l[1]);
    reinterpret_cast<__half2*>(lo + o)[1] = __half2(l[2], l[3]);
}

__global__ void convx_kernel(const float* __restrict__ x) {
    int i = blockIdx.y;
    if (i >= g_na) return;
    int r = g_act[i];
    int d = (blockIdx.x * 256 + threadIdx.x) * 4;
    float4 v = *reinterpret_cast<const float4*>(x + (size_t)r * DD + d);
    float vv[4] = {v.x, v.y, v.z, v.w};
    bf h[4], l[4];
#pragma unroll
    for (int j = 0; j < 4; ++j) split_bf16(vv[j], h[j], l[j]);
    size_t o = (size_t)i * DD + d;
    reinterpret_cast<__nv_bfloat162*>(g_xah + o)[0] = __nv_bfloat162(h[0], h[1]);
    reinterpret_cast<__nv_bfloat162*>(g_xah + o)[1] = __nv_bfloat162(h[2], h[3]);
    reinterpret_cast<__nv_bfloat162*>(g_xal + o)[0] = __nv_bfloat162(l[0], l[1]);
    reinterpret_cast<__nv_bfloat162*>(g_xal + o)[1] = __nv_bfloat162(l[2], l[3]);
}
__global__ void convpT_kernel(const float* __restrict__ P) {
    __shared__ float tile[32][33];
    int d0 = blockIdx.x * 32, p0 = blockIdx.y * 32;
    int tx = threadIdx.x, ty = threadIdx.y;
#pragma unroll
    for (int i = 0; i < 4; ++i)
        tile[ty + i * 8][tx] = P[(size_t)(p0 + ty + i * 8) * DD + d0 + tx];
    __syncthreads();
#pragma unroll
    for (int i = 0; i < 4; ++i) {
        hf h, l;
        split_f16(tile[tx][ty + i * 8], h, l);
        size_t o = (size_t)(d0 + ty + i * 8) * PP + p0 + tx;
        g_pTfh[o] = h; g_pTfl[o] = l;
    }
}
__global__ void concatb_kernel(const float* __restrict__ a, const float* __restrict__ b) {
    int i = blockIdx.x * 256 + threadIdx.x;   // interleaved: even=bm, odd=bl
    g_bcat[i] = (i & 1) ? b[i >> 1] : a[i >> 1];
}

// ================= bf16 3-product GEMM (G1, G2) =================
// flags: 1=Meff from g_na, 2=relu, 8=hi/lo out, 16=var/w (w -> fp16 Chf + f32 outputs)
#define ROWB 144
#define TILE_B (128 * ROWB)
#define STAGE_B (4 * TILE_B)
#define NSTG 3
#define SMEMB (NSTG * STAGE_B + 512)

__global__ void __launch_bounds__(512, 1)
gemm_mma(const bf* __restrict__ Ah, const bf* __restrict__ Al,
         const bf* __restrict__ Bh, const bf* __restrict__ Bl,
         const float* __restrict__ bias, float* __restrict__ Cf,
         bf* __restrict__ Ch, bf* __restrict__ Cl, hf* __restrict__ Chf,
         float* __restrict__ Cw, const float* __restrict__ eps,
         int M, int N, int K, int flags)
{
    int Meff = (flags & 1) ? g_na : M;
    int mT = blockIdx.y * 128;
    if (mT >= Meff) return;
    int nT = blockIdx.x * 128;

    extern __shared__ char sm[];
    uint32_t sb = smem_u32(sm);
    float* biasS = reinterpret_cast<float*>(sm + NSTG * STAGE_B);

    int tid = threadIdx.x, wid = tid >> 5, lane = tid & 31;
    int wm = wid & 3, wn = wid >> 2;

    if (tid < 128) {
        int n = nT + tid;
        biasS[tid] = (bias && n < N) ? bias[n] : 0.0f;
    }

    uint32_t aBase = (wm * 32 + (lane & 15)) * ROWB + ((lane >> 4) & 1) * 16;
    uint32_t bBase = 2 * TILE_B + (wn * 32 + ((lane >> 4) & 1) * 8 + (lane & 7)) * ROWB +
                     ((lane >> 3) & 1) * 16;

    float acc[2][4][4];
#pragma unroll
    for (int a = 0; a < 2; ++a)
#pragma unroll
        for (int b = 0; b < 4; ++b)
#pragma unroll
            for (int c = 0; c < 4; ++c) acc[a][b][c] = 0.0f;

    int nK = K / 64;

#define LOAD_STAGE(s, k0)                                                        \
    {                                                                            \
        uint32_t st = sb + (s) * STAGE_B;                                        \
        _Pragma("unroll")                                                        \
        for (int i = 0; i < 2; ++i) {                                            \
            int idx = i * 512 + tid;                                             \
            int r = idx >> 3, c16 = idx & 7;                                     \
            int rg = mT + r; rg = rg < Meff ? rg : Meff - 1;                     \
            size_t go = (size_t)rg * K + (k0) + c16 * 8;                         \
            uint32_t off = r * ROWB + c16 * 16;                                  \
            cpa16(st + off, Ah + go);                                            \
            cpa16(st + TILE_B + off, Al + go);                                   \
        }                                                                        \
        _Pragma("unroll")                                                        \
        for (int i = 0; i < 2; ++i) {                                            \
            int idx = i * 512 + tid;                                             \
            int r = idx >> 3, c16 = idx & 7;                                     \
            int rg = nT + r; rg = rg < N ? rg : N - 1;                           \
            size_t go = (size_t)rg * K + (k0) + c16 * 8;                         \
            uint32_t off = r * ROWB + c16 * 16;                                  \
            cpa16(st + 2 * TILE_B + off, Bh + go);                               \
            cpa16(st + 3 * TILE_B + off, Bl + go);                               \
        }                                                                        \
    }

#define LOAD_FRAGS(st, kh, AH, AL, BH, BL)                                       \
    {                                                                            \
        uint32_t ab = (st) + aBase + (kh) * 32;                                  \
        _Pragma("unroll")                                                        \
        for (int ma = 0; ma < 2; ++ma) {                                         \
            ldmx4(AH[ma], ab + ma * 16 * ROWB);                                  \
            ldmx4(AL[ma], ab + ma * 16 * ROWB + TILE_B);                         \
        }                                                                        \
        uint32_t bb = (st) + bBase + (kh) * 32;                                  \
        _Pragma("unroll")                                                        \
        for (int p = 0; p < 2; ++p) {                                            \
            uint32_t t[4];                                                       \
            ldmx4(t, bb + p * 16 * ROWB);                                        \
            BH[2*p][0] = t[0]; BH[2*p][1] = t[1];                                \
            BH[2*p+1][0] = t[2]; BH[2*p+1][1] = t[3];                            \
            ldmx4(t, bb + p * 16 * ROWB + TILE_B);                               \
            BL[2*p][0] = t[0]; BL[2*p][1] = t[1];                                \
            BL[2*p+1][0] = t[2]; BL[2*p+1][1] = t[3];                            \
        }                                                                        \
    }

#define MMA_BLOCK(AH, AL, BH, BL)                                                \
    {                                                                            \
        _Pragma("unroll")                                                        \
        for (int ma = 0; ma < 2; ++ma)                                           \
            _Pragma("unroll")                                                    \
            for (int na = 0; na < 4; ++na) mma16816(acc[ma][na], AH[ma], BH[na]);\
        _Pragma("unroll")                                                        \
        for (int ma = 0; ma < 2; ++ma)                                           \
            _Pragma("unroll")                                                    \
            for (int na = 0; na < 4; ++na) mma16816(acc[ma][na], AH[ma], BL[na]);\
        _Pragma("unroll")                                                        \
        for (int ma = 0; ma < 2; ++ma)                                           \
            _Pragma("unroll")                                                    \
            for (int na = 0; na < 4; ++na) mma16816(acc[ma][na], AL[ma], BH[na]);\
    }

    LOAD_STAGE(0, 0);
    asm volatile("cp.async.commit_group;");
    LOAD_STAGE(1, 64);
    asm volatile("cp.async.commit_group;");

    uint32_t a0h[2][4], a0l[2][4], b0h[4][2], b0l[4][2];
    uint32_t a1h[2][4], a1l[2][4], b1h[4][2], b1l[4][2];

    asm volatile("cp.async.wait_group 1;");
    __syncthreads();
    LOAD_FRAGS(sb, 0, a0h, a0l, b0h, b0l);

    int s_cur = 0;
#pragma unroll 1
    for (int it = 0; it < nK; ++it) {
        uint32_t st = sb + s_cur * STAGE_B;
        LOAD_FRAGS(st, 1, a1h, a1l, b1h, b1l);
        MMA_BLOCK(a0h, a0l, b0h, b0l);
        LOAD_FRAGS(st, 2, a0h, a0l, b0h, b0l);
        MMA_BLOCK(a1h, a1l, b1h, b1l);
        LOAD_FRAGS(st, 3, a1h, a1l, b1h, b1l);
        MMA_BLOCK(a0h, a0l, b0h, b0l);
        int ps = it + 2;
        int s_tgt = s_cur + 2 >= NSTG ? s_cur + 2 - NSTG : s_cur + 2;
        if (ps < nK) LOAD_STAGE(s_tgt, ps * 64);
        asm volatile("cp.async.commit_group;");
        asm volatile("cp.async.wait_group 1;");
        __syncthreads();
        if (it + 1 < nK) {
            int s_n = s_cur + 1 == NSTG ? 0 : s_cur + 1;
            uint32_t st2 = sb + s_n * STAGE_B;
            LOAD_FRAGS(st2, 0, a0h, a0l, b0h, b0l);
        }
        MMA_BLOCK(a1h, a1l, b1h, b1l);
        s_cur = s_cur + 1 == NSTG ? 0 : s_cur + 1;
    }

    // ---- epilogue ----
    bool relu = flags & 2, hilos = flags & 8, varw = flags & 16;
#pragma unroll
    for (int ma = 0; ma < 2; ++ma) {
#pragma unroll
        for (int rs = 0; rs < 2; ++rs) {
            int m = mT + wm * 32 + ma * 16 + (lane >> 2) + rs * 8;
            if (m >= Meff) continue;
            size_t ro = (size_t)m * N;
            int r = varw ? g_act[m] : 0;
#pragma unroll
            for (int na = 0; na < 4; ++na) {
                int nc = wn * 32 + na * 8 + (lane & 3) * 2;
                int n = nT + nc;
                if (n >= N) continue;
                float v0 = acc[ma][na][rs * 2 + 0] + biasS[nc];
                float v1 = acc[ma][na][rs * 2 + 1] + biasS[nc + 1];
                if (relu) { v0 = fmaxf(v0, 0.0f); v1 = fmaxf(v1, 0.0f); }
                if (varw) {
                    float var0 = expf(v0), var1 = expf(v1);
                    float w0 = 1.0f + sqrtf(var0) * eps[(size_t)r * N + n];
                    float w1 = 1.0f + sqrtf(var1) * eps[(size_t)r * N + n + 1];
                    int np = g_newpos[r];
                    if (np >= BB / 2) {          // miss row -> direct f32 outputs
                        size_t jo = (size_t)(np - BB / 2) * N + n;
                        *reinterpret_cast<float2*>(Cf + jo) = make_float2(var0, var1);
                        *reinterpret_cast<float2*>(Cw + jo) = make_float2(w0, w1);
                    }
                    *reinterpret_cast<__half2*>(Chf + ro + n) = __floats2half2_rn(w0, w1);
                } else if (hilos) {
                    bf h0, l0, h1, l1;
                    split_bf16(v0, h0, l0); split_bf16(v1, h1, l1);
                    *reinterpret_cast<__nv_bfloat162*>(Ch + ro + n) = __nv_bfloat162(h0, h1);
                    *reinterpret_cast<__nv_bfloat162*>(Cl + ro + n) = __nv_bfloat162(l0, l1);
                }
            }
        }
    }
}

// ================= fp16 2-product GEMM (G3, G4, G9, G11, G12) =================
// A plain fp16, B fp16 hi/lo. flags: 1=Meff g_na, 2=relu, 4=f32 out, 8=fp16 out, 16=dual-xreg
#define TILE_F (128 * ROWB)
#define STAGE_F (3 * TILE_F)     // A, Bh, Bl
#define SMEMF (NSTG * STAGE_F + 512)

__global__ void __launch_bounds__(512, 1)
gemm_f16(const hf* __restrict__ A, const hf* __restrict__ Bh, const hf* __restrict__ Bl,
         const float* __restrict__ bias, float* __restrict__ Cf, hf* __restrict__ Chf,
         const float* __restrict__ eps, int M, int N, int K, int flags)
{
    int Meff = (flags & 1) ? g_na : M;
    int mT = blockIdx.y * 128;
    if (mT >= Meff) return;
    int nT = blockIdx.x * 128;

    extern __shared__ char sm[];
    uint32_t sb = smem_u32(sm);
    float* biasS = reinterpret_cast<float*>(sm + NSTG * STAGE_F);

    int tid = threadIdx.x, wid = tid >> 5, lane = tid & 31;
    int wm = wid & 3, wn = wid >> 2;

    if (tid < 128) {
        int n = nT + tid;
        biasS[tid] = (bias && n < N) ? bias[n] : 0.0f;
    }

    uint32_t aBase = (wm * 32 + (lane & 15)) * ROWB + ((lane >> 4) & 1) * 16;
    uint32_t bBase = TILE_F + (wn * 32 + ((lane >> 4) & 1) * 8 + (lane & 7)) * ROWB +
                     ((lane >> 3) & 1) * 16;

    float acc[2][4][4];
#pragma unroll
    for (int a = 0; a < 2; ++a)
#pragma unroll
        for (int b = 0; b < 4; ++b)
#pragma unroll
            for (int c = 0; c < 4; ++c) acc[a][b][c] = 0.0f;

    int nK = K / 64;

#define LOAD_STAGE_F(s, k0)                                                      \
    {                                                                            \
        uint32_t st = sb + (s) * STAGE_F;                                        \
        _Pragma("unroll")                                                        \
        for (int i = 0; i < 2; ++i) {                                            \
            int idx = i * 512 + tid;                                             \
            int r = idx >> 3, c16 = idx & 7;                                     \
            int rg = mT + r; rg = rg < Meff ? rg : Meff - 1;                     \
            size_t go = (size_t)rg * K + (k0) + c16 * 8;                         \
            cpa16(st + r * ROWB + c16 * 16, A + go);                             \
        }                                                                        \
        _Pragma("unroll")                                                        \
        for (int i = 0; i < 2; ++i) {                                            \
            int idx = i * 512 + tid;                                             \
            int r = idx >> 3, c16 = idx & 7;                                     \
            int rg = nT + r; rg = rg < N ? rg : N - 1;                           \
            size_t go = (size_t)rg * K + (k0) + c16 * 8;                         \
            uint32_t off = r * ROWB + c16 * 16;                                  \
            cpa16(st + TILE_F + off, Bh + go);                                   \
            cpa16(st + 2 * TILE_F + off, Bl + go);                               \
        }                                                                        \
    }

#define LOAD_FRAGS_F(st, kh, AR, BH, BL)                                         \
    {                                                                            \
        uint32_t ab = (st) + aBase + (kh) * 32;                                  \
        _Pragma("unroll")                                                        \
        for (int ma = 0; ma < 2; ++ma) ldmx4(AR[ma], ab + ma * 16 * ROWB);       \
        uint32_t bb = (st) + bBase + (kh) * 32;                                  \
        _Pragma("unroll")                                                        \
        for (int p = 0; p < 2; ++p) {                                            \
            uint32_t t[4];                                                       \
            ldmx4(t, bb + p * 16 * ROWB);                                        \
            BH[2*p][0] = t[0]; BH[2*p][1] = t[1];                                \
            BH[2*p+1][0] = t[2]; BH[2*p+1][1] = t[3];                            \
            ldmx4(t, bb + p * 16 * ROWB + TILE_F);                               \
            BL[2*p][0] = t[0]; BL[2*p][1] = t[1];                                \
            BL[2*p+1][0] = t[2]; BL[2*p+1][1] = t[3];                            \
        }                                                                        \
    }

#define MMA_BLOCK_F(AR, BH, BL)                                                  \
    {                                                                            \
        _Pragma("unroll")                                                        \
        for (int ma = 0; ma < 2; ++ma)                                           \
            _Pragma("unroll")                                                    \
            for (int na = 0; na < 4; ++na) mma16816h(acc[ma][na], AR[ma], BH[na]);\
        _Pragma("unroll")                                                        \
        for (int ma = 0; ma < 2; ++ma)                                           \
            _Pragma("unroll")                                                    \
            for (int na = 0; na < 4; ++na) mma16816h(acc[ma][na], AR[ma], BL[na]);\
    }

    LOAD_STAGE_F(0, 0);
    asm volatile("cp.async.commit_group;");
    LOAD_STAGE_F(1, 64);
    asm volatile("cp.async.commit_group;");

    uint32_t a0[2][4], b0h[4][2], b0l[4][2];
    uint32_t a1[2][4], b1h[4][2], b1l[4][2];

    asm volatile("cp.async.wait_group 1;");
    __syncthreads();
    LOAD_FRAGS_F(sb, 0, a0, b0h, b0l);

    int s_cur = 0;
#pragma unroll 1
    for (int it = 0; it < nK; ++it) {
        uint32_t st = sb + s_cur * STAGE_F;
        LOAD_FRAGS_F(st, 1, a1, b1h, b1l);
        MMA_BLOCK_F(a0, b0h, b0l);
        LOAD_FRAGS_F(st, 2, a0, b0h, b0l);
        MMA_BLOCK_F(a1, b1h, b1l);
        LOAD_FRAGS_F(st, 3, a1, b1h, b1l);
        MMA_BLOCK_F(a0, b0h, b0l);
        int ps = it + 2;
        int s_tgt = s_cur + 2 >= NSTG ? s_cur + 2 - NSTG : s_cur + 2;
        if (ps < nK) LOAD_STAGE_F(s_tgt, ps * 64);
        asm volatile("cp.async.commit_group;");
        asm volatile("cp.async.wait_group 1;");
        __syncthreads();
        if (it + 1 < nK) {
            int s_n = s_cur + 1 == NSTG ? 0 : s_cur + 1;
            uint32_t st2 = sb + s_n * STAGE_F;
            LOAD_FRAGS_F(st2, 0, a0, b0h, b0l);
        }
        MMA_BLOCK_F(a1, b1h, b1l);
        s_cur = s_cur + 1 == NSTG ? 0 : s_cur + 1;
    }

    bool relu = flags & 2, f32s = flags & 4, hfs = flags & 8, dual = flags & 16;
#pragma unroll
    for (int ma = 0; ma < 2; ++ma) {
#pragma unroll
        for (int rs = 0; rs < 2; ++rs) {
            int m = mT + wm * 32 + ma * 16 + (lane >> 2) + rs * 8;
            if (m >= Meff) continue;
            size_t ro = (size_t)m * N;
            int r = dual ? g_act[m] : 0;
#pragma unroll
            for (int na = 0; na < 4; ++na) {
                int nc = wn * 32 + na * 8 + (lane & 3) * 2;
                int n = nT + nc;
                if (n >= N) continue;
                float v0 = acc[ma][na][rs * 2 + 0] + biasS[nc];
                float v1 = acc[ma][na][rs * 2 + 1] + biasS[nc + 1];
                if (relu) { v0 = fmaxf(v0, 0.0f); v1 = fmaxf(v1, 0.0f); }
                if (dual) {
                    // interleaved Wm/Wl: v0 = mean_d, v1 = lreg_d, d = n/2
                    if (g_mask[r]) {
                        int d = n >> 1;
                        float xr = Cf[(size_t)m * DD + d];           // x_rec f32
                        float ep = eps[(size_t)r * DD + d];          // eps_r
                        float o = xr * softplusf(v0 + expf(0.5f * v1) * ep);
                        size_t dst = (size_t)g_newpos[r] * DD + d;
                        Chf[dst] = __float2half_rn(o);
                    }
                } else {
                    if (f32s)
                        *reinterpret_cast<float2*>(Cf + ro + n) = make_float2(v0, v1);
                    if (hfs)
                        *reinterpret_cast<__half2*>(Chf + ro + n) = __floats2half2_rn(v0, v1);
                }
            }
        }
    }
}

// ---- elementwise ----
__global__ void copy_kernel(const float* __restrict__ x) {
    int j = blockIdx.y;
    int r = g_perm[j];
    if (g_mask[r]) return;
    int d = (blockIdx.x * 256 + threadIdx.x) * 4;
    float4 v = *reinterpret_cast<const float4*>(x + (size_t)r * DD + d);
    size_t dst = (size_t)j * DD + d;
    reinterpret_cast<__half2*>(g_cbf + dst)[0] = __floats2half2_rn(v.x, v.y);
    reinterpret_cast<__half2*>(g_cbf + dst)[1] = __floats2half2_rn(v.z, v.w);
}

// ---- launch ----
static void* sa(const void* s) { void* p = nullptr; cudaGetSymbolAddress(&p, s); return p; }

extern "C" void kernel_launch(void* const* d_in, const int* in_sizes, int n_in,
                              void* d_out, int out_size) {
    const float* x      = (const float*)d_in[0];
    const int*   mm     = (const int*)d_in[1];
    const float* priors = (const float*)d_in[2];
    const float* W1  = (const float*)d_in[3];
    const float* b1  = (const float*)d_in[4];
    const float* W2  = (const float*)d_in[5];
    const float* b2  = (const float*)d_in[6];
    const float* Wr1 = (const float*)d_in[7];
    const float* br1 = (const float*)d_in[8];
    const float* Wlv = (const float*)d_in[9];
    const float* blv = (const float*)d_in[10];
    const float* Wg1 = (const float*)d_in[11];
    const float* bg1 = (const float*)d_in[12];
    const float* Wm  = (const float*)d_in[13];
    const float* bm  = (const float*)d_in[14];
    const float* Wl  = (const float*)d_in[15];
    const float* bl  = (const float*)d_in[16];
    const float* eps_w = (const float*)d_in[17];
    const float* eps_r = (const float*)d_in[18];
    float* out = (float*)d_out;
    float* out_logits = out;
    float* out_w = out + (size_t)BB * OO;
    float* out_var = out_w + (size_t)(BB - BB / 2) * PP;

    cudaFuncSetAttribute(gemm_mma, cudaFuncAttributeMaxDynamicSharedMemorySize, SMEMB);
    cudaFuncSetAttribute(gemm_f16, cudaFuncAttributeMaxDynamicSharedMemorySize, SMEMF);

    bf *Wr1h=(bf*)sa(g_Wr1h), *Wr1l=(bf*)sa(g_Wr1l), *Wlvh=(bf*)sa(g_Wlvh), *Wlvl=(bf*)sa(g_Wlvl);
    bf *xah=(bf*)sa(g_xah), *xal=(bf*)sa(g_xal), *hh=(bf*)sa(g_hh), *hl=(bf*)sa(g_hl);
    hf *Wg1fh=(hf*)sa(g_Wg1fh), *Wg1fl=(hf*)sa(g_Wg1fl);
    hf *Wcfh=(hf*)sa(g_Wcfh), *Wcfl=(hf*)sa(g_Wcfl);
    hf *W1fh=(hf*)sa(g_W1fh), *W1fl=(hf*)sa(g_W1fl);
    hf *W2fh=(hf*)sa(g_W2fh), *W2fl=(hf*)sa(g_W2fl);
    hf *pTfh=(hf*)sa(g_pTfh), *pTfl=(hf*)sa(g_pTfl);
    hf *wvf=(hf*)sa(g_wvf), *xrf=(hf*)sa(g_xrf), *hrf=(hf*)sa(g_hrf);
    hf *cbf=(hf*)sa(g_cbf), *h1f=(hf*)sa(g_h1f);
    float *pxrecf=(float*)sa(g_xrecf);
    float *pbcat=(float*)sa(g_bcat);

    dim3 blk(512);

    setup_kernel<<<1, 1024>>>(mm);                                  // 0
    convx_kernel<<<dim3(DD/1024, BB), 256>>>(x);                    // 1
    convw_all<<<dim3(16384, 7), 256>>>(Wr1, Wlv, Wg1, Wm, Wl, W1, W2); // 2
    // 3) h = relu(xa @ Wr1^T + br1) -> bf16 hi/lo   [FIX: relu bit restored]
    gemm_mma<<<dim3(HH/128, BB/128), blk, SMEMB>>>(xah, xal, Wr1h, Wr1l, br1,
        nullptr, hh, hl, nullptr, nullptr, nullptr, BB, HH, DD, 1|2|8);
    // 4) var/w: f32 outputs for miss rows + w -> fp16 wvf
    gemm_mma<<<dim3(PP/128, BB/128), blk, SMEMB>>>(hh, hl, Wlvh, Wlvl, blv,
        out_var, nullptr, nullptr, wvf, out_w, eps_w, BB, PP, HH, 1|16);
    convpT_kernel<<<dim3(DD/32, PP/32), dim3(32, 8)>>>(priors);     // 5
    // 6) x_rec = w @ pT^T -> f32 + fp16   [fp16 2-product]
    gemm_f16<<<dim3(DD/128, BB/128), blk, SMEMF>>>(wvf, pTfh, pTfl, nullptr,
        pxrecf, xrf, nullptr, BB, DD, PP, 1|4|8);
    // 7) hr = relu(x_rec @ Wg1^T + bg1) -> fp16   [fp16 2-product]
    gemm_f16<<<dim3(HH/128, BB/128), blk, SMEMF>>>(xrf, Wg1fh, Wg1fl, bg1,
        nullptr, hrf, nullptr, BB, HH, DD, 1|2|8);
    concatb_kernel<<<(2*DD)/256, 256>>>(bm, bl);                    // 8
    // 9) fused dual: interleaved [mean|lreg] -> x_reg scatter into cbf   [fp16 2-product]
    gemm_f16<<<dim3((2*DD)/128, BB/128), blk, SMEMF>>>(hrf, Wcfh, Wcfl, pbcat,
        pxrecf, cbf, eps_r, BB, 2*DD, HH, 1|16);
    copy_kernel<<<dim3(DD/1024, BB), 256>>>(x);                     // 10
    // 11) h1 = relu(comb @ W1^T + b1) -> fp16   [fp16 2-product]
    gemm_f16<<<dim3(HH/128, BB/128), blk, SMEMF>>>(cbf, W1fh, W1fl, b1,
        nullptr, h1f, nullptr, BB, HH, DD, 2|8);
    // 12) logits = h1 @ W2^T + b2 -> f32   [fp16 2-product]
    gemm_f16<<<dim3((OO+127)/128, BB/128), blk, SMEMF>>>(h1f, W2fh, W2fl, b2,
        out_logits, nullptr, nullptr, BB, OO, HH, 4);
}

// round 14
// speedup vs baseline: 1.5940x; 1.0297x over previous
#include <cuda_runtime.h>
#include <cuda_bf16.h>
#include <cuda_fp16.h>
#include <cstdint>

#define BB 4096
#define DD 4096
#define HH 4096
#define OO 1000
#define PP 2048

typedef __half hf;

// ---- device scratch (all fp16 tier now) ----
__device__ hf g_Wr1fh[(size_t)HH*DD], g_Wr1fl[(size_t)HH*DD];
__device__ hf g_Wlvfh[(size_t)PP*HH], g_Wlvfl[(size_t)PP*HH];
__device__ hf g_Wg1fh[(size_t)HH*DD], g_Wg1fl[(size_t)HH*DD];
__device__ hf g_Wcfh [(size_t)2*DD*HH], g_Wcfl [(size_t)2*DD*HH]; // Wm/Wl row-interleaved
__device__ hf g_W1fh[(size_t)HH*DD], g_W1fl[(size_t)HH*DD];
__device__ hf g_W2fh[(size_t)OO*HH], g_W2fl[(size_t)OO*HH];
__device__ hf g_pTfh[(size_t)DD*PP], g_pTfl[(size_t)DD*PP];
__device__ hf g_xf  [(size_t)BB*DD];
__device__ hf g_hf  [(size_t)BB*HH];
__device__ hf g_wvf [(size_t)BB*PP];
__device__ hf g_xrf [(size_t)BB*DD];
__device__ hf g_hrf [(size_t)BB*HH];
__device__ hf g_cbf [(size_t)BB*DD];
__device__ hf g_h1f [(size_t)BB*HH];
__device__ float g_bcat[2*DD];
__device__ int g_na, g_perm[BB], g_newpos[BB], g_act[BB], g_posinact[BB], g_mask[BB];

// ---- helpers ----
__device__ __forceinline__ float softplusf(float z) {
    return fmaxf(z, 0.0f) + log1pf(expf(-fabsf(z)));
}
__device__ __forceinline__ uint32_t smem_u32(const void* p) {
    uint32_t a;
    asm("{ .reg .u64 t; cvta.to.shared.u64 t, %1; cvt.u32.u64 %0, t; }" : "=r"(a) : "l"(p));
    return a;
}
__device__ __forceinline__ void cpa16(uint32_t dst, const void* src) {
    asm volatile("cp.async.cg.shared.global [%0], [%1], 16;" :: "r"(dst), "l"(src));
}
__device__ __forceinline__ void ldmx4(uint32_t* r, uint32_t a) {
    asm volatile("ldmatrix.sync.aligned.m8n8.x4.shared.b16 {%0,%1,%2,%3}, [%4];"
                 : "=r"(r[0]), "=r"(r[1]), "=r"(r[2]), "=r"(r[3]) : "r"(a));
}
__device__ __forceinline__ void mma16816h(float* c, const uint32_t* a, const uint32_t* b) {
    asm("mma.sync.aligned.m16n8k16.row.col.f32.f16.f16.f32 "
        "{%0,%1,%2,%3}, {%4,%5,%6,%7}, {%8,%9}, {%0,%1,%2,%3};"
        : "+f"(c[0]), "+f"(c[1]), "+f"(c[2]), "+f"(c[3])
        : "r"(a[0]), "r"(a[1]), "r"(a[2]), "r"(a[3]), "r"(b[0]), "r"(b[1]));
}
__device__ __forceinline__ void split_f16(float v, hf& h, hf& l) {
    h = __float2half_rn(v);
    l = __float2half_rn(v - __half2float(h));
}

// ---- setup ----
__global__ void setup_kernel(const int* __restrict__ mm) {
    __shared__ int wsum[32];
    __shared__ int sTot[2];
    int tid = threadIdx.x, lane = tid & 31, warp = tid >> 5;
    int base = tid * 4;
    int f[4], incl[4], s = 0;
#pragma unroll
    for (int j = 0; j < 4; ++j) { f[j] = (mm[base + j] % 2 != 0); s += f[j]; incl[j] = s; }
    int v = s;
#pragma unroll
    for (int o = 1; o < 32; o <<= 1) { int u = __shfl_up_sync(~0u, v, o); if (lane >= o) v += u; }
    if (lane == 31) wsum[warp] = v;
    __syncthreads();
    if (warp == 0) {
        int w = wsum[lane];
#pragma unroll
        for (int o = 1; o < 32; o <<= 1) { int u = __shfl_up_sync(~0u, w, o); if (lane >= o) w += u; }
        wsum[lane] = w;
        if (lane == 31) sTot[0] = w;
    }
    __syncthreads();
    int Z = BB - sTot[0];
    int thrExcl = (warp ? wsum[warp - 1] : 0) + (v - s);
    int af[4];
#pragma unroll
    for (int j = 0; j < 4; ++j) {
        int i = base + j;
        int ones = thrExcl + incl[j] - f[j];
        int pos = f[j] ? (Z + ones) : (i - ones);
        g_mask[i] = f[j]; g_newpos[i] = pos; g_perm[pos] = i;
        af[j] = (f[j] || pos >= BB / 2);
    }
    __syncthreads();
    int incl2[4], s2 = 0;
#pragma unroll
    for (int j = 0; j < 4; ++j) { s2 += af[j]; incl2[j] = s2; }
    int v2 = s2;
#pragma unroll
    for (int o = 1; o < 32; o <<= 1) { int u = __shfl_up_sync(~0u, v2, o); if (lane >= o) v2 += u; }
    if (lane == 31) wsum[warp] = v2;
    __syncthreads();
    if (warp == 0) {
        int w = wsum[lane];
#pragma unroll
        for (int o = 1; o < 32; o <<= 1) { int u = __shfl_up_sync(~0u, w, o); if (lane >= o) w += u; }
        wsum[lane] = w;
        if (lane == 31) sTot[1] = w;
    }
    __syncthreads();
    int thrExcl2 = (warp ? wsum[warp - 1] : 0) + (v2 - s2);
#pragma unroll
    for (int j = 0; j < 4; ++j) {
        int i = base + j;
        int ab = thrExcl2 + incl2[j] - af[j];
        if (af[j]) { g_act[ab] = i; g_posinact[i] = ab; } else g_posinact[i] = -1;
    }
    if (tid == 0) g_na = sTot[1];
}

// ---- batched weight conversion (all fp16 hi/lo) ----
__global__ void convw_all(const float* __restrict__ Wr1, const float* __restrict__ Wlv,
                          const float* __restrict__ Wg1, const float* __restrict__ Wm,
                          const float* __restrict__ Wl,  const float* __restrict__ W1,
                          const float* __restrict__ W2) {
    int seg = blockIdx.y;
    size_t i = ((size_t)blockIdx.x * 256 + threadIdx.x) * 4;
    const float* src;
    size_t n;
    switch (seg) {
        case 0: src = Wr1; n = (size_t)HH * DD; break;
        case 1: src = Wg1; n = (size_t)HH * DD; break;
        case 2: src = W1;  n = (size_t)HH * DD; break;
        case 3: src = Wlv; n = (size_t)PP * HH; break;
        case 4: src = W2;  n = (size_t)OO * HH; break;
        case 5: src = Wm;  n = (size_t)DD * HH; break;
        default: src = Wl; n = (size_t)DD * HH; break;
    }
    if (i >= n) return;
    float4 v = *reinterpret_cast<const float4*>(src + i);
    float vv[4] = {v.x, v.y, v.z, v.w};
    hf *hi, *lo;
    size_t o = i;
    switch (seg) {
        case 0: hi = g_Wr1fh; lo = g_Wr1fl; break;
        case 1: hi = g_Wg1fh; lo = g_Wg1fl; break;
        case 2: hi = g_W1fh;  lo = g_W1fl;  break;
        case 3: hi = g_Wlvfh; lo = g_Wlvfl; break;
        case 4: hi = g_W2fh;  lo = g_W2fl;  break;
        default: {   // 5, 6: Wm/Wl interleaved (even rows = Wm, odd = Wl)
            hi = g_Wcfh; lo = g_Wcfl;
            size_t row = i / HH, col = i - row * HH;
            o = (row * 2 + (seg - 5)) * HH + col;
        }
    }
    hf h[4], l[4];
#pragma unroll
    for (int j = 0; j < 4; ++j) split_f16(vv[j], h[j], l[j]);
    reinterpret_cast<__half2*>(hi + o)[0] = __half2(h[0], h[1]);
    reinterpret_cast<__half2*>(hi + o)[1] = __half2(h[2], h[3]);
    reinterpret_cast<__half2*>(lo + o)[0] = __half2(l[0], l[1]);
    reinterpret_cast<__half2*>(lo + o)[1] = __half2(l[2], l[3]);
}

__global__ void convx_kernel(const float* __restrict__ x) {
    int i = blockIdx.y;
    if (i >= g_na) return;
    int r = g_act[i];
    int d = (blockIdx.x * 256 + threadIdx.x) * 4;
    float4 v = *reinterpret_cast<const float4*>(x + (size_t)r * DD + d);
    size_t o = (size_t)i * DD + d;
    reinterpret_cast<__half2*>(g_xf + o)[0] = __floats2half2_rn(v.x, v.y);
    reinterpret_cast<__half2*>(g_xf + o)[1] = __floats2half2_rn(v.z, v.w);
}
__global__ void convpT_kernel(const float* __restrict__ P) {
    __shared__ float tile[32][33];
    int d0 = blockIdx.x * 32, p0 = blockIdx.y * 32;
    int tx = threadIdx.x, ty = threadIdx.y;
#pragma unroll
    for (int i = 0; i < 4; ++i)
        tile[ty + i * 8][tx] = P[(size_t)(p0 + ty + i * 8) * DD + d0 + tx];
    __syncthreads();
#pragma unroll
    for (int i = 0; i < 4; ++i) {
        hf h, l;
        split_f16(tile[tx][ty + i * 8], h, l);
        size_t o = (size_t)(d0 + ty + i * 8) * PP + p0 + tx;
        g_pTfh[o] = h; g_pTfl[o] = l;
    }
}
__global__ void concatb_kernel(const float* __restrict__ a, const float* __restrict__ b) {
    int i = blockIdx.x * 256 + threadIdx.x;   // interleaved: even=bm, odd=bl
    g_bcat[i] = (i & 1) ? b[i >> 1] : a[i >> 1];
}

// ================= fp16 2-product GEMM (all 8 GEMMs) =================
// C[M,N] = A @ (Bh+Bl)^T + bias. A plain fp16, B fp16 hi/lo.
// 128x128 CTA tile, BK=64, 3-stage, 512 threads, 1 CTA/SM.
// flags: 1=Meff g_na, 2=relu, 4=f32 out (Cf), 8=fp16 out (Chf),
//        16=dual-xreg (reads Xr, eps; scatters fp16 into Chf),
//        32=var/w (exp epilogue; f32 out_var->Cf, out_w->Cw for miss rows; w fp16->Chf)
#define ROWB 144
#define TILE_F (128 * ROWB)
#define STAGE_F (3 * TILE_F)     // A, Bh, Bl
#define NSTG 3
#define SMEMF (NSTG * STAGE_F + 512)

__global__ void __launch_bounds__(512, 1)
gemm_f16(const hf* __restrict__ A, const hf* __restrict__ Bh, const hf* __restrict__ Bl,
         const float* __restrict__ bias, float* __restrict__ Cf, hf* __restrict__ Chf,
         float* __restrict__ Cw, const float* __restrict__ eps, const hf* __restrict__ Xr,
         int M, int N, int K, int flags)
{
    int Meff = (flags & 1) ? g_na : M;
    int mT = blockIdx.y * 128;
    if (mT >= Meff) return;
    int nT = blockIdx.x * 128;

    extern __shared__ char sm[];
    uint32_t sb = smem_u32(sm);
    float* biasS = reinterpret_cast<float*>(sm + NSTG * STAGE_F);

    int tid = threadIdx.x, wid = tid >> 5, lane = tid & 31;
    int wm = wid & 3, wn = wid >> 2;

    if (tid < 128) {
        int n = nT + tid;
        biasS[tid] = (bias && n < N) ? bias[n] : 0.0f;
    }

    uint32_t aBase = (wm * 32 + (lane & 15)) * ROWB + ((lane >> 4) & 1) * 16;
    uint32_t bBase = TILE_F + (wn * 32 + ((lane >> 4) & 1) * 8 + (lane & 7)) * ROWB +
                     ((lane >> 3) & 1) * 16;

    float acc[2][4][4];
#pragma unroll
    for (int a = 0; a < 2; ++a)
#pragma unroll
        for (int b = 0; b < 4; ++b)
#pragma unroll
            for (int c = 0; c < 4; ++c) acc[a][b][c] = 0.0f;

    int nK = K / 64;

#define LOAD_STAGE_F(s, k0)                                                      \
    {                                                                            \
        uint32_t st = sb + (s) * STAGE_F;                                        \
        _Pragma("unroll")                                                        \
        for (int i = 0; i < 2; ++i) {                                            \
            int idx = i * 512 + tid;                                             \
            int r = idx >> 3, c16 = idx & 7;                                     \
            int rg = mT + r; rg = rg < Meff ? rg : Meff - 1;                     \
            size_t go = (size_t)rg * K + (k0) + c16 * 8;                         \
            cpa16(st + r * ROWB + c16 * 16, A + go);                             \
        }                                                                        \
        _Pragma("unroll")                                                        \
        for (int i = 0; i < 2; ++i) {                                            \
            int idx = i * 512 + tid;                                             \
            int r = idx >> 3, c16 = idx & 7;                                     \
            int rg = nT + r; rg = rg < N ? rg : N - 1;                           \
            size_t go = (size_t)rg * K + (k0) + c16 * 8;                         \
            uint32_t off = r * ROWB + c16 * 16;                                  \
            cpa16(st + TILE_F + off, Bh + go);                                   \
            cpa16(st + 2 * TILE_F + off, Bl + go);                               \
        }                                                                        \
    }

#define LOAD_FRAGS_F(st, kh, AR, BH, BL)                                         \
    {                                                                            \
        uint32_t ab = (st) + aBase + (kh) * 32;                                  \
        _Pragma("unroll")                                                        \
        for (int ma = 0; ma < 2; ++ma) ldmx4(AR[ma], ab + ma * 16 * ROWB);       \
        uint32_t bb = (st) + bBase + (kh) * 32;                                  \
        _Pragma("unroll")                                                        \
        for (int p = 0; p < 2; ++p) {                                            \
            uint32_t t[4];                                                       \
            ldmx4(t, bb + p * 16 * ROWB);                                        \
            BH[2*p][0] = t[0]; BH[2*p][1] = t[1];                                \
            BH[2*p+1][0] = t[2]; BH[2*p+1][1] = t[3];                            \
            ldmx4(t, bb + p * 16 * ROWB + TILE_F);                               \
            BL[2*p][0] = t[0]; BL[2*p][1] = t[1];                                \
            BL[2*p+1][0] = t[2]; BL[2*p+1][1] = t[3];                            \
        }                                                                        \
    }

#define MMA_BLOCK_F(AR, BH, BL)                                                  \
    {                                                                            \
        _Pragma("unroll")                                                        \
        for (int ma = 0; ma < 2; ++ma)                                           \
            _Pragma("unroll")                                                    \
            for (int na = 0; na < 4; ++na) mma16816h(acc[ma][na], AR[ma], BH[na]);\
        _Pragma("unroll")                                                        \
        for (int ma = 0; ma < 2; ++ma)                                           \
            _Pragma("unroll")                                                    \
            for (int na = 0; na < 4; ++na) mma16816h(acc[ma][na], AR[ma], BL[na]);\
    }

    LOAD_STAGE_F(0, 0);
    asm volatile("cp.async.commit_group;");
    LOAD_STAGE_F(1, 64);
    asm volatile("cp.async.commit_group;");

    uint32_t a0[2][4], b0h[4][2], b0l[4][2];
    uint32_t a1[2][4], b1h[4][2], b1l[4][2];

    asm volatile("cp.async.wait_group 1;");
    __syncthreads();
    LOAD_FRAGS_F(sb, 0, a0, b0h, b0l);

    int s_cur = 0;
#pragma unroll 1
    for (int it = 0; it < nK; ++it) {
        uint32_t st = sb + s_cur * STAGE_F;
        LOAD_FRAGS_F(st, 1, a1, b1h, b1l);
        MMA_BLOCK_F(a0, b0h, b0l);
        LOAD_FRAGS_F(st, 2, a0, b0h, b0l);
        MMA_BLOCK_F(a1, b1h, b1l);
        LOAD_FRAGS_F(st, 3, a1, b1h, b1l);
        MMA_BLOCK_F(a0, b0h, b0l);
        int ps = it + 2;
        int s_tgt = s_cur + 2 >= NSTG ? s_cur + 2 - NSTG : s_cur + 2;
        if (ps < nK) LOAD_STAGE_F(s_tgt, ps * 64);
        asm volatile("cp.async.commit_group;");
        asm volatile("cp.async.wait_group 1;");
        __syncthreads();
        if (it + 1 < nK) {
            int s_n = s_cur + 1 == NSTG ? 0 : s_cur + 1;
            uint32_t st2 = sb + s_n * STAGE_F;
            LOAD_FRAGS_F(st2, 0, a0, b0h, b0l);
        }
        MMA_BLOCK_F(a1, b1h, b1l);
        s_cur = s_cur + 1 == NSTG ? 0 : s_cur + 1;
    }

    // ---- epilogue ----
    bool relu = flags & 2, f32s = flags & 4, hfs = flags & 8;
    bool dual = flags & 16, varw = flags & 32;
#pragma unroll
    for (int ma = 0; ma < 2; ++ma) {
#pragma unroll
        for (int rs = 0; rs < 2; ++rs) {
            int m = mT + wm * 32 + ma * 16 + (lane >> 2) + rs * 8;
            if (m >= Meff) continue;
            size_t ro = (size_t)m * N;
            int r = (dual || varw) ? g_act[m] : 0;
#pragma unroll
            for (int na = 0; na < 4; ++na) {
                int nc = wn * 32 + na * 8 + (lane & 3) * 2;
                int n = nT + nc;
                if (n >= N) continue;
                float v0 = acc[ma][na][rs * 2 + 0] + biasS[nc];
                float v1 = acc[ma][na][rs * 2 + 1] + biasS[nc + 1];
                if (relu) { v0 = fmaxf(v0, 0.0f); v1 = fmaxf(v1, 0.0f); }
                if (varw) {
                    float var0 = expf(v0), var1 = expf(v1);
                    float w0 = 1.0f + sqrtf(var0) * eps[(size_t)r * N + n];
                    float w1 = 1.0f + sqrtf(var1) * eps[(size_t)r * N + n + 1];
                    int np = g_newpos[r];
                    if (np >= BB / 2) {          // miss row -> direct f32 outputs
                        size_t jo = (size_t)(np - BB / 2) * N + n;
                        *reinterpret_cast<float2*>(Cf + jo) = make_float2(var0, var1);
                        *reinterpret_cast<float2*>(Cw + jo) = make_float2(w0, w1);
                    }
                    *reinterpret_cast<__half2*>(Chf + ro + n) = __floats2half2_rn(w0, w1);
                } else if (dual) {
                    // interleaved Wm/Wl: v0 = mean_d, v1 = lreg_d, d = n/2
                    if (g_mask[r]) {
                        int d = n >> 1;
                        float xr = __half2float(Xr[(size_t)m * DD + d]);
                        float ep = eps[(size_t)r * DD + d];
                        float o = xr * softplusf(v0 + expf(0.5f * v1) * ep);
                        size_t dst = (size_t)g_newpos[r] * DD + d;
                        Chf[dst] = __float2half_rn(o);
                    }
                } else {
                    if (f32s)
                        *reinterpret_cast<float2*>(Cf + ro + n) = make_float2(v0, v1);
                    if (hfs)
                        *reinterpret_cast<__half2*>(Chf + ro + n) = __floats2half2_rn(v0, v1);
                }
            }
        }
    }
}

// ---- elementwise ----
__global__ void copy_kernel(const float* __restrict__ x) {
    int j = blockIdx.y;
    int r = g_perm[j];
    if (g_mask[r]) return;
    int d = (blockIdx.x * 256 + threadIdx.x) * 4;
    float4 v = *reinterpret_cast<const float4*>(x + (size_t)r * DD + d);
    size_t dst = (size_t)j * DD + d;
    reinterpret_cast<__half2*>(g_cbf + dst)[0] = __floats2half2_rn(v.x, v.y);
    reinterpret_cast<__half2*>(g_cbf + dst)[1] = __floats2half2_rn(v.z, v.w);
}

// ---- launch ----
static void* sa(const void* s) { void* p = nullptr; cudaGetSymbolAddress(&p, s); return p; }

extern "C" void kernel_launch(void* const* d_in, const int* in_sizes, int n_in,
                              void* d_out, int out_size) {
    const float* x      = (const float*)d_in[0];
    const int*   mm     = (const int*)d_in[1];
    const float* priors = (const float*)d_in[2];
    const float* W1  = (const float*)d_in[3];
    const float* b1  = (const float*)d_in[4];
    const float* W2  = (const float*)d_in[5];
    const float* b2  = (const float*)d_in[6];
    const float* Wr1 = (const float*)d_in[7];
    const float* br1 = (const float*)d_in[8];
    const float* Wlv = (const float*)d_in[9];
    const float* blv = (const float*)d_in[10];
    const float* Wg1 = (const float*)d_in[11];
    const float* bg1 = (const float*)d_in[12];
    const float* Wm  = (const float*)d_in[13];
    const float* bm  = (const float*)d_in[14];
    const float* Wl  = (const float*)d_in[15];
    const float* bl  = (const float*)d_in[16];
    const float* eps_w = (const float*)d_in[17];
    const float* eps_r = (const float*)d_in[18];
    float* out = (float*)d_out;
    float* out_logits = out;
    float* out_w = out + (size_t)BB * OO;
    float* out_var = out_w + (size_t)(BB - BB / 2) * PP;

    cudaFuncSetAttribute(gemm_f16, cudaFuncAttributeMaxDynamicSharedMemorySize, SMEMF);

    hf *Wr1fh=(hf*)sa(g_Wr1fh), *Wr1fl=(hf*)sa(g_Wr1fl);
    hf *Wlvfh=(hf*)sa(g_Wlvfh), *Wlvfl=(hf*)sa(g_Wlvfl);
    hf *Wg1fh=(hf*)sa(g_Wg1fh), *Wg1fl=(hf*)sa(g_Wg1fl);
    hf *Wcfh=(hf*)sa(g_Wcfh), *Wcfl=(hf*)sa(g_Wcfl);
    hf *W1fh=(hf*)sa(g_W1fh), *W1fl=(hf*)sa(g_W1fl);
    hf *W2fh=(hf*)sa(g_W2fh), *W2fl=(hf*)sa(g_W2fl);
    hf *pTfh=(hf*)sa(g_pTfh), *pTfl=(hf*)sa(g_pTfl);
    hf *xf=(hf*)sa(g_xf), *hff=(hf*)sa(g_hf);
    hf *wvf=(hf*)sa(g_wvf), *xrf=(hf*)sa(g_xrf), *hrf=(hf*)sa(g_hrf);
    hf *cbf=(hf*)sa(g_cbf), *h1f=(hf*)sa(g_h1f);
    float *pbcat=(float*)sa(g_bcat);

    dim3 blk(512);

    setup_kernel<<<1, 1024>>>(mm);                                  // 0
    convx_kernel<<<dim3(DD/1024, BB), 256>>>(x);                    // 1
    convw_all<<<dim3(16384, 7), 256>>>(Wr1, Wlv, Wg1, Wm, Wl, W1, W2); // 2
    // 3) h = relu(xf @ Wr1^T + br1) -> fp16   [PROFILED LAUNCH]
    gemm_f16<<<dim3(HH/128, BB/128), blk, SMEMF>>>(xf, Wr1fh, Wr1fl, br1,
        nullptr, hff, nullptr, nullptr, nullptr, BB, HH, DD, 1|2|8);
    // 4) var/w: f32 outputs for miss rows + w -> fp16 wvf
    gemm_f16<<<dim3(PP/128, BB/128), blk, SMEMF>>>(hff, Wlvfh, Wlvfl, blv,
        out_var, wvf, out_w, eps_w, nullptr, BB, PP, HH, 1|32);
    convpT_kernel<<<dim3(DD/32, PP/32), dim3(32, 8)>>>(priors);     // 5
    // 6) x_rec = w @ pT^T -> fp16
    gemm_f16<<<dim3(DD/128, BB/128), blk, SMEMF>>>(wvf, pTfh, pTfl, nullptr,
        nullptr, xrf, nullptr, nullptr, nullptr, BB, DD, PP, 1|8);
    // 7) hr = relu(x_rec @ Wg1^T + bg1) -> fp16
    gemm_f16<<<dim3(HH/128, BB/128), blk, SMEMF>>>(xrf, Wg1fh, Wg1fl, bg1,
        nullptr, hrf, nullptr, nullptr, nullptr, BB, HH, DD, 1|2|8);
    concatb_kernel<<<(2*DD)/256, 256>>>(bm, bl);                    // 8
    // 9) fused dual: interleaved [mean|lreg] -> x_reg scatter into cbf
    gemm_f16<<<dim3((2*DD)/128, BB/128), blk, SMEMF>>>(hrf, Wcfh, Wcfl, pbcat,
        nullptr, cbf, nullptr, eps_r, xrf, BB, 2*DD, HH, 1|16);
    copy_kernel<<<dim3(DD/1024, BB), 256>>>(x);                     // 10
    // 11) h1 = relu(comb @ W1^T + b1) -> fp16
    gemm_f16<<<dim3(HH/128, BB/128), blk, SMEMF>>>(cbf, W1fh, W1fl, b1,
        nullptr, h1f, nullptr, nullptr, nullptr, BB, HH, DD, 2|8);
    // 12) logits = h1 @ W2^T + b2 -> f32
    gemm_f16<<<dim3((OO+127)/128, BB/128), blk, SMEMF>>>(h1f, W2fh, W2fl, b2,
        out_logits, nullptr, nullptr, nullptr, nullptr, BB, OO, HH, 4);
}